// round 6
// baseline (speedup 1.0000x reference)
#include <cuda_runtime.h>
#include <cuda_fp16.h>
#include <math.h>
#include <stdint.h>

// Problem dims
constexpr int BB = 64;
constexpr int TT = 32;
constexpr int SS = 31;     // scan steps (T-1)
constexpr int VV = 10000;
constexpr int EE = 300;
constexpr int HH = 256;
constexpr int FF = 4096;
constexpr int GG = 1024;   // 4*H
constexpr int KIN = HH + EE;   // 556
constexpr int KAP = 576;       // KIN padded to 32-multiple
constexpr int MROWS = SS * BB; // 1984
constexpr int NB = 79;         // fc2 N tiles

// -------------------- device scratch (static, no allocs) --------------------
__device__ float  d_Xp[BB * HH];
__device__ float  d_xpart[16 * BB * HH];
__device__ __half d_Acat[MROWS * KAP];     // [Xp | emb | 0] fp16
__device__ float  d_bias2[GG];             // b_ih + b_hh
__device__ float  d_gpre[MROWS * GG];      // precomputed gate inputs (fp32)
__device__ __half d_Hall[MROWS * HH];      // h history fp16 (fc2 A matrix)
__device__ float  d_logits[MROWS * VV];
__device__ int    d_labels[TT * BB];
__device__ __half d_w2h[VV * HH];          // fc2_w fp16
__device__ __half d_wihh[GG * KAP];        // w_ih fp16, K-padded
__device__ float2 d_part[MROWS * NB];      // per-tile (max, sumexp) partials
__device__ float  d_lz[MROWS];             // log-partition per row
__device__ unsigned bar_cnt4[4];           // per-group arrival counters

// -------------------- helpers ------------------------------------------------
__device__ __forceinline__ void cp16(void* smem_dst, const void* gsrc, bool pred) {
    uint32_t saddr = (uint32_t)__cvta_generic_to_shared(smem_dst);
    int sz = pred ? 16 : 0;
    asm volatile("cp.async.cg.shared.global [%0], [%1], 16, %2;\n"
                 :: "r"(saddr), "l"(gsrc), "r"(sz) : "memory");
}
__device__ __forceinline__ void mma_f16(float* d, const uint32_t* a, const uint32_t* b) {
    asm volatile(
        "mma.sync.aligned.m16n8k16.row.col.f32.f16.f16.f32 "
        "{%0,%1,%2,%3}, {%4,%5,%6,%7}, {%8,%9}, {%0,%1,%2,%3};"
        : "+f"(d[0]), "+f"(d[1]), "+f"(d[2]), "+f"(d[3])
        : "r"(a[0]), "r"(a[1]), "r"(a[2]), "r"(a[3]), "r"(b[0]), "r"(b[1]));
}
__device__ __forceinline__ void arrive_rel(unsigned* p) {
    asm volatile("red.add.release.gpu.u32 [%0], 1;" :: "l"(p) : "memory");
}
__device__ __forceinline__ unsigned ld_acq(unsigned* p) {
    unsigned v;
    asm volatile("ld.acquire.gpu.u32 %0, [%1];" : "=r"(v) : "l"(p) : "memory");
    return v;
}
__device__ __forceinline__ uint2 pack_h4(float4 v) {
    __half2 p0 = __floats2half2_rn(v.x, v.y);
    __half2 p1 = __floats2half2_rn(v.z, v.w);
    uint2 u;
    u.x = *(uint32_t*)&p0;
    u.y = *(uint32_t*)&p1;
    return u;
}

// -------------------- prep: labels + combined bias + barrier reset -----------
__global__ void k_prep(const int* __restrict__ lab,
                       const float* __restrict__ bih,
                       const float* __restrict__ bhh) {
    __shared__ int is64;
    if (threadIdx.x == 0) {
        int f = 1;
        for (int i = 1; i < 64 && f; i += 2)
            if (lab[i] != 0) f = 0;
        is64 = f;
    }
    if (threadIdx.x < 4) bar_cnt4[threadIdx.x] = 0;   // reset per graph replay
    __syncthreads();
    for (int i = threadIdx.x; i < TT * BB; i += blockDim.x)
        d_labels[i] = is64 ? (int)(((const long long*)lab)[i]) : lab[i];
    for (int i = threadIdx.x; i < GG; i += blockDim.x)
        d_bias2[i] = bih[i] + bhh[i];
}

// -------------------- fc1: Xp = X @ fc1_w.T + b (split-K SIMT) ---------------
__global__ void __launch_bounds__(256) k_fc1(const float* __restrict__ X,
                                             const float* __restrict__ W) {
    const int h0 = blockIdx.x * 32;
    const int kb = blockIdx.y;
    const int kbase = kb * 256;
    const int tid = threadIdx.x;
    __shared__ __align__(16) float Xs[32][68];
    __shared__ float Wsh[32][33];
    float acc[4][2];
#pragma unroll
    for (int q = 0; q < 4; q++) { acc[q][0] = 0.f; acc[q][1] = 0.f; }
    const int tb = (tid & 15) * 4;
    const int th = (tid >> 4) * 2;

    for (int t = 0; t < 8; t++) {
        int k0 = kbase + t * 32;
#pragma unroll
        for (int i = 0; i < 8; i++) {
            int idx = tid + i * 256;
            int b = idx >> 5, kk = idx & 31;
            Xs[kk][b] = X[(size_t)b * FF + k0 + kk];
        }
#pragma unroll
        for (int i = 0; i < 4; i++) {
            int idx = tid + i * 256;
            int hh = idx >> 5, kk = idx & 31;
            Wsh[kk][hh] = W[(size_t)(h0 + hh) * FF + k0 + kk];
        }
        __syncthreads();
#pragma unroll
        for (int kk = 0; kk < 32; kk++) {
            float4 x4 = *(const float4*)&Xs[kk][tb];
            float w0 = Wsh[kk][th], w1 = Wsh[kk][th + 1];
            acc[0][0] += x4.x * w0; acc[0][1] += x4.x * w1;
            acc[1][0] += x4.y * w0; acc[1][1] += x4.y * w1;
            acc[2][0] += x4.z * w0; acc[2][1] += x4.z * w1;
            acc[3][0] += x4.w * w0; acc[3][1] += x4.w * w1;
        }
        __syncthreads();
    }
#pragma unroll
    for (int q = 0; q < 4; q++)
#pragma unroll
        for (int j = 0; j < 2; j++)
            d_xpart[kb * (BB * HH) + (tb + q) * HH + h0 + th + j] = acc[q][j];
}

__global__ void k_fc1red(const float* __restrict__ fc1_b) {
    int i4 = blockIdx.x * 256 + threadIdx.x;
    if (i4 < BB * HH / 4) {
        const float4* bp = (const float4*)fc1_b;
        float4 s = bp[i4 & 63];
#pragma unroll
        for (int kb = 0; kb < 16; kb++) {
            float4 p = ((const float4*)(d_xpart + kb * BB * HH))[i4];
            s.x += p.x; s.y += p.y; s.z += p.z; s.w += p.w;
        }
        ((float4*)d_Xp)[i4] = s;
    }
}

// -------------------- merged elementwise: buildA + wih cvt + fc2w cvt --------
constexpr int AC4 = KAP / 4;               // 144 groups per row
constexpr int R1 = MROWS * AC4;            // 285696
constexpr int R2 = GG * AC4;               // 147456
constexpr int R3 = VV * HH / 4;            // 640000
constexpr int RALL = R1 + R2 + R3;         // 1073152  (divisible by 256)
__global__ void __launch_bounds__(256) k_cvtall(const float* __restrict__ emb_table,
                                                const float* __restrict__ wih,
                                                const float* __restrict__ fc2w) {
    int idx = blockIdx.x * 256 + threadIdx.x;
    if (idx < R1) {                        // Acat = [Xp | emb | 0]
        int r = idx / AC4, c = idx - r * AC4;
        int s = r >> 6, b = r & 63;
        float4 v;
        if (c < 64) {
            v = ((const float4*)d_Xp)[b * 64 + c];
        } else if (c < 139) {
            int tok = (s == 0) ? 1 : d_labels[s * BB + b];   // START_ID = 1
            v = *(const float4*)(emb_table + (size_t)tok * EE + (c - 64) * 4);
        } else {
            v = make_float4(0.f, 0.f, 0.f, 0.f);
        }
        ((uint2*)d_Acat)[idx] = pack_h4(v);
    } else if (idx < R1 + R2) {            // w_ih -> fp16, K-padded
        int i = idx - R1;
        int r = i / AC4, c = i - r * AC4;
        float4 v = (c < 139) ? *(const float4*)(wih + (size_t)r * KIN + c * 4)
                             : make_float4(0.f, 0.f, 0.f, 0.f);
        ((uint2*)d_wihh)[i] = pack_h4(v);
    } else if (idx < RALL) {               // fc2_w -> fp16
        int i = idx - (R1 + R2);
        ((uint2*)d_w2h)[i] = pack_h4(((const float4*)fc2w)[i]);
    }
}

// -------------------- fp16 tensor-core GEMM ----------------------------------
// C[M,N] = A[M,K] @ B[N,K]^T + bias[N]; 128x128 tile, BK=32, 8 warps.
// SMPART: epilogue also emits per-row online (max, sumexp) partials over the
// tile's columns into d_part[row][blockIdx.x] (biased values stored to C).
template <bool SMPART>
__global__ void __launch_bounds__(256) k_hgemm(
    const __half* __restrict__ A, int lda,
    const __half* __restrict__ B, int ldb,
    const float* __restrict__ bias,
    float* __restrict__ C, int ldc,
    int M, int N, int K)
{
    __shared__ __align__(16) __half As[2][128][40];
    __shared__ __align__(16) __half Bs[2][128][40];
    __shared__ float2 sm_p[128][2];

    const int tid = threadIdx.x;
    const int lane = tid & 31;
    const int warpId = tid >> 5;
    const int warpM = warpId & 3;
    const int warpN = warpId >> 2;
    const int g = lane >> 2;
    const int t = lane & 3;

    const int ncol = blockIdx.x * 128;
    const int mrow = blockIdx.y * 128;

    float acc[2][8][4];
#pragma unroll
    for (int mt = 0; mt < 2; mt++)
#pragma unroll
        for (int nt = 0; nt < 8; nt++)
#pragma unroll
            for (int q = 0; q < 4; q++) acc[mt][nt][q] = 0.f;

    const int NT = K >> 5;

    auto load_tile = [&](int buf, int kt) {
        int k0 = kt << 5;
#pragma unroll
        for (int i = 0; i < 2; i++) {
            int c = tid + i * 256;
            int m = c >> 2, kc = (c & 3) * 8;
            cp16(&As[buf][m][kc], A + (size_t)(mrow + m) * lda + k0 + kc,
                 (mrow + m) < M);
        }
#pragma unroll
        for (int i = 0; i < 2; i++) {
            int c = tid + i * 256;
            int n = c >> 2, kc = (c & 3) * 8;
            cp16(&Bs[buf][n][kc], B + (size_t)(ncol + n) * ldb + k0 + kc,
                 (ncol + n) < N);
        }
    };

    load_tile(0, 0);
    asm volatile("cp.async.commit_group;\n" ::: "memory");

    for (int kt = 0; kt < NT; kt++) {
        int buf = kt & 1;
        if (kt + 1 < NT) {
            load_tile(buf ^ 1, kt + 1);
            asm volatile("cp.async.commit_group;\n" ::: "memory");
            asm volatile("cp.async.wait_group 1;\n" ::: "memory");
        } else {
            asm volatile("cp.async.wait_group 0;\n" ::: "memory");
        }
        __syncthreads();

#pragma unroll
        for (int ks = 0; ks < 32; ks += 16) {
            uint32_t afr[2][4], bfr[8][2];
#pragma unroll
            for (int mt = 0; mt < 2; mt++) {
                int r0 = warpM * 32 + mt * 16;
                afr[mt][0] = *(const uint32_t*)&As[buf][r0 + g][ks + 2 * t];
                afr[mt][1] = *(const uint32_t*)&As[buf][r0 + g + 8][ks + 2 * t];
                afr[mt][2] = *(const uint32_t*)&As[buf][r0 + g][ks + 2 * t + 8];
                afr[mt][3] = *(const uint32_t*)&As[buf][r0 + g + 8][ks + 2 * t + 8];
            }
#pragma unroll
            for (int nt = 0; nt < 8; nt++) {
                int c0 = warpN * 64 + nt * 8;
                bfr[nt][0] = *(const uint32_t*)&Bs[buf][c0 + g][ks + 2 * t];
                bfr[nt][1] = *(const uint32_t*)&Bs[buf][c0 + g][ks + 2 * t + 8];
            }
#pragma unroll
            for (int mt = 0; mt < 2; mt++)
#pragma unroll
                for (int nt = 0; nt < 8; nt++)
                    mma_f16(acc[mt][nt], afr[mt], bfr[nt]);
        }
        __syncthreads();
    }

    if (!SMPART) {
        // plain epilogue: bias + store
#pragma unroll
        for (int mt = 0; mt < 2; mt++) {
#pragma unroll
            for (int nt = 0; nt < 8; nt++) {
                int m0 = mrow + warpM * 32 + mt * 16 + g;
                int n0 = ncol + warpN * 64 + nt * 8 + 2 * t;
                if (n0 < N) {
                    float b0 = bias[n0], b1 = bias[n0 + 1];
                    if (m0 < M) {
                        C[(size_t)m0 * ldc + n0]     = acc[mt][nt][0] + b0;
                        C[(size_t)m0 * ldc + n0 + 1] = acc[mt][nt][1] + b1;
                    }
                    if (m0 + 8 < M) {
                        C[(size_t)(m0 + 8) * ldc + n0]     = acc[mt][nt][2] + b0;
                        C[(size_t)(m0 + 8) * ldc + n0 + 1] = acc[mt][nt][3] + b1;
                    }
                }
            }
        }
        return;
    }

    // epilogue with softmax partials: bias into acc, store, per-row (max,sumexp)
#pragma unroll
    for (int mt = 0; mt < 2; mt++) {
        float mA = -1e30f, mB = -1e30f;
#pragma unroll
        for (int nt = 0; nt < 8; nt++) {
            int n0 = ncol + warpN * 64 + nt * 8 + 2 * t;
            bool ok = n0 < N;
            float b0 = ok ? bias[n0] : 0.f;
            float b1 = ok ? bias[n0 + 1] : 0.f;
            float v0 = ok ? acc[mt][nt][0] + b0 : -1e30f;
            float v1 = ok ? acc[mt][nt][1] + b1 : -1e30f;
            float v2 = ok ? acc[mt][nt][2] + b0 : -1e30f;
            float v3 = ok ? acc[mt][nt][3] + b1 : -1e30f;
            acc[mt][nt][0] = v0; acc[mt][nt][1] = v1;
            acc[mt][nt][2] = v2; acc[mt][nt][3] = v3;
            mA = fmaxf(mA, fmaxf(v0, v1));
            mB = fmaxf(mB, fmaxf(v2, v3));
        }
        float sA = 0.f, sB = 0.f;
#pragma unroll
        for (int nt = 0; nt < 8; nt++) {
            int n0 = ncol + warpN * 64 + nt * 8 + 2 * t;
            bool ok = n0 < N;
            if (ok) {
                sA += __expf(acc[mt][nt][0] - mA) + __expf(acc[mt][nt][1] - mA);
                sB += __expf(acc[mt][nt][2] - mB) + __expf(acc[mt][nt][3] - mB);
            }
            // store biased values
            int m0 = mrow + warpM * 32 + mt * 16 + g;
            if (ok) {
                if (m0 < M) {
                    C[(size_t)m0 * ldc + n0]     = acc[mt][nt][0];
                    C[(size_t)m0 * ldc + n0 + 1] = acc[mt][nt][1];
                }
                if (m0 + 8 < M) {
                    C[(size_t)(m0 + 8) * ldc + n0]     = acc[mt][nt][2];
                    C[(size_t)(m0 + 8) * ldc + n0 + 1] = acc[mt][nt][3];
                }
            }
        }
        // quad reduce across t (lanes xor 1, 2)
#pragma unroll
        for (int o = 1; o <= 2; o <<= 1) {
            float mo = __shfl_xor_sync(0xffffffffu, mA, o);
            float so = __shfl_xor_sync(0xffffffffu, sA, o);
            float M2 = fmaxf(mA, mo);
            sA = sA * __expf(mA - M2) + so * __expf(mo - M2);
            mA = M2;
            mo = __shfl_xor_sync(0xffffffffu, mB, o);
            so = __shfl_xor_sync(0xffffffffu, sB, o);
            M2 = fmaxf(mB, mo);
            sB = sB * __expf(mB - M2) + so * __expf(mo - M2);
            mB = M2;
        }
        if (t == 0) {
            int rA = warpM * 32 + mt * 16 + g;
            sm_p[rA][warpN]     = make_float2(mA, sA);
            sm_p[rA + 8][warpN] = make_float2(mB, sB);
        }
    }
    __syncthreads();
    if (tid < 128) {
        int row = mrow + tid;
        if (row < M) {
            float2 p0 = sm_p[tid][0], p1 = sm_p[tid][1];
            float M2 = fmaxf(p0.x, p1.x);
            float S = p0.y * __expf(p0.x - M2) + p1.y * __expf(p1.x - M2);
            d_part[(size_t)row * NB + blockIdx.x] = make_float2(M2, S);
        }
    }
}

// -------------------- recurrence: 4 batch-groups x 16 j-blocks ---------------
// Monotonic counter barrier (release arrive / acquire spin); gpre for the next
// step is prefetched into registers inside the barrier-wait shadow.
__global__ void __launch_bounds__(256, 1) k_rec(const float* __restrict__ w_hh) {
    __shared__ __align__(16) __half hs[16][264];   // h_prev (16 rows x 256)
    __shared__ float gbuf[16][68];                 // gate exchange

    const int tid = threadIdx.x;
    const int lane = tid & 31;
    const int wid = tid >> 5;
    const int g = lane >> 2;
    const int t = lane & 3;
    const int jb = blockIdx.x & 15;
    const int grp = blockIdx.x >> 4;
    const int j0 = jb * 16;
    const int brow0 = grp * 16;

    // preload w_hh fragments (fp16, 32 regs)
    uint32_t wb[16][2];
    {
        int lc = wid * 8 + g;                           // local col 0..63
        int wrow = (lc >> 4) * 256 + j0 + (lc & 15);    // gate*256 + j
        const float* wr = w_hh + (size_t)wrow * HH;
#pragma unroll
        for (int kt = 0; kt < 16; kt++) {
            __half2 h0 = __floats2half2_rn(wr[kt * 16 + 2 * t], wr[kt * 16 + 2 * t + 1]);
            __half2 h1 = __floats2half2_rn(wr[kt * 16 + 2 * t + 8], wr[kt * 16 + 2 * t + 9]);
            wb[kt][0] = *(uint32_t*)&h0;
            wb[kt][1] = *(uint32_t*)&h1;
        }
    }

    float creg = 0.f;
    const int cb = tid >> 4, cj = tid & 15;
    const int lc = wid * 8 + 2 * t;
    const int r0 = (lc >> 4) * 256 + j0 + (lc & 15);
    unsigned* cnt = &bar_cnt4[grp];

    // prefetch gpre for s=0
    const float* gp0 = d_gpre + (size_t)brow0 * GG;
    float2 g0 = *(const float2*)&gp0[(size_t)g * GG + r0];
    float2 g1 = *(const float2*)&gp0[(size_t)(g + 8) * GG + r0];

    for (int s = 0; s < SS; s++) {
        float acc[4] = {0.f, 0.f, 0.f, 0.f};

        if (s > 0) {
            const uint4* src = (const uint4*)(d_Hall + ((size_t)(s - 1) * BB + brow0) * HH);
#pragma unroll
            for (int i = 0; i < 2; i++) {
                int c = tid + i * 256;
                int m = c >> 5, kc = c & 31;
                *(uint4*)&hs[m][kc * 8] = src[m * 32 + kc];
            }
            __syncthreads();
#pragma unroll
            for (int kt = 0; kt < 16; kt++) {
                uint32_t af[4];
                af[0] = *(const uint32_t*)&hs[g][kt * 16 + 2 * t];
                af[1] = *(const uint32_t*)&hs[g + 8][kt * 16 + 2 * t];
                af[2] = *(const uint32_t*)&hs[g][kt * 16 + 2 * t + 8];
                af[3] = *(const uint32_t*)&hs[g + 8][kt * 16 + 2 * t + 8];
                mma_f16(acc, af, wb[kt]);
            }
        }

        gbuf[g][lc]         = acc[0] + g0.x;
        gbuf[g][lc + 1]     = acc[1] + g0.y;
        gbuf[g + 8][lc]     = acc[2] + g1.x;
        gbuf[g + 8][lc + 1] = acc[3] + g1.y;
        __syncthreads();

        {
            float gi = gbuf[cb][cj],      gf = gbuf[cb][16 + cj];
            float gc = gbuf[cb][32 + cj], go = gbuf[cb][48 + cj];
            float ii = 1.f / (1.f + expf(-gi));
            float ff = 1.f / (1.f + expf(-gf));
            float gv = tanhf(gc);
            float oo = 1.f / (1.f + expf(-go));
            float cn = ff * creg + ii * gv;
            creg = cn;
            d_Hall[((size_t)s * BB + brow0 + cb) * HH + j0 + cj] =
                __float2half(oo * tanhf(cn));
        }

        if (s + 1 < SS) {
            if (tid == 0) arrive_rel(cnt);
            // prefetch next step's gpre while the barrier drains
            const float* gp = d_gpre + ((size_t)(s + 1) * BB + brow0) * GG;
            g0 = *(const float2*)&gp[(size_t)g * GG + r0];
            g1 = *(const float2*)&gp[(size_t)(g + 8) * GG + r0];
            if (tid == 0) {
                unsigned target = 16u * (unsigned)(s + 1);
                while (ld_acq(cnt) < target) {}
            }
            __syncthreads();
        }
    }
}

// -------------------- lz reduction: 79 partials per row ----------------------
__global__ void __launch_bounds__(256) k_lzred() {
    int r = blockIdx.x * 8 + (threadIdx.x >> 5);
    int lane = threadIdx.x & 31;
    if (r >= MROWS) return;
    float m = -1e30f, s = 0.f;
    for (int nb = lane; nb < NB; nb += 32) {
        float2 p = d_part[(size_t)r * NB + nb];
        float M = fmaxf(m, p.x);
        s = s * __expf(m - M) + p.y * __expf(p.x - M);
        m = M;
    }
#pragma unroll
    for (int o = 16; o; o >>= 1) {
        float mo = __shfl_xor_sync(0xffffffffu, m, o);
        float so = __shfl_xor_sync(0xffffffffu, s, o);
        float M = fmaxf(m, mo);
        s = s * __expf(m - M) + so * __expf(mo - M);
        m = M;
    }
    if (lane == 0) d_lz[r] = m + logf(s);
}

// -------------------- output: subtract lz + transpose + one-hot --------------
__global__ void __launch_bounds__(256) k_out(float* __restrict__ out) {
    const int r = blockIdx.x;
    const int tid = threadIdx.x;
    if (r >= MROWS) {
        int b = r - MROWS;
        float* dst = out + (size_t)b * TT * VV;
        for (int v = tid; v < VV; v += 256) dst[v] = (v == 1) ? 1.f : 0.f;
        return;
    }
    const int s = r >> 6, b = r & 63;
    const float lz = d_lz[r];
    const float4* src = (const float4*)(d_logits + (size_t)r * VV);
    float4* dst = (float4*)(out + ((size_t)b * TT + s + 1) * VV);
    for (int c = tid; c < VV / 4; c += 256) {
        float4 x = src[c];
        x.x -= lz; x.y -= lz; x.z -= lz; x.w -= lz;
        dst[c] = x;
    }
}

// -------------------- launch ------------------------------------------------
extern "C" void kernel_launch(void* const* d_in, const int* in_sizes, int n_in,
                              void* d_out, int out_size) {
    const float* X    = (const float*)d_in[0];
    const float* emb  = (const float*)d_in[1];
    const float* fc1w = (const float*)d_in[2];
    const float* fc1b = (const float*)d_in[3];
    const float* wih  = (const float*)d_in[4];
    const float* whh  = (const float*)d_in[5];
    const float* bih  = (const float*)d_in[6];
    const float* bhh  = (const float*)d_in[7];
    const float* fc2w = (const float*)d_in[8];
    const float* fc2b = (const float*)d_in[9];
    const int*   lab  = (const int*)d_in[10];
    float* out = (float*)d_out;

    __half *pAcat, *pHall, *pW2h, *pWihh;
    float *pBias2, *pGpre, *pLogits;
    cudaGetSymbolAddress((void**)&pAcat,   d_Acat);
    cudaGetSymbolAddress((void**)&pBias2,  d_bias2);
    cudaGetSymbolAddress((void**)&pGpre,   d_gpre);
    cudaGetSymbolAddress((void**)&pHall,   d_Hall);
    cudaGetSymbolAddress((void**)&pLogits, d_logits);
    cudaGetSymbolAddress((void**)&pW2h,    d_w2h);
    cudaGetSymbolAddress((void**)&pWihh,   d_wihh);

    // 1..5: prep chain (k_rec is launch #6 -> profiled by ncu -s 5 -c 1)
    k_prep<<<1, 256>>>(lab, bih, bhh);
    k_fc1<<<dim3(8, 16), 256>>>(X, fc1w);
    k_fc1red<<<16, 256>>>(fc1b);
    k_cvtall<<<RALL / 256, 256>>>(emb, wih, fc2w);

    // gpre: [1984,1024] = Acat[1984,576] @ wihh[1024,576]^T + (bih+bhh)
    k_hgemm<false><<<dim3(8, 16), 256>>>(pAcat, KAP, pWihh, KAP, pBias2,
                                         pGpre, GG, MROWS, GG, KAP);

    // recurrence: 64 blocks = 4 batch-groups x 16 j-blocks
    k_rec<<<64, 256>>>(whh);

    // fc2 + softmax partials: logits = Hall @ w2h^T + fc2b
    k_hgemm<true><<<dim3(NB, 16), 256>>>(pHall, HH, pW2h, HH, fc2b,
                                         pLogits, VV, MROWS, VV, HH);

    k_lzred<<<MROWS / 8, 256>>>();
    k_out<<<MROWS + BB, 256>>>(out);
}

// round 7
// speedup vs baseline: 1.2990x; 1.2990x over previous
#include <cuda_runtime.h>
#include <cuda_fp16.h>
#include <math.h>
#include <stdint.h>

// Problem dims
constexpr int BB = 64;
constexpr int TT = 32;
constexpr int SS = 31;     // scan steps (T-1)
constexpr int VV = 10000;
constexpr int EE = 300;
constexpr int HH = 256;
constexpr int FF = 4096;
constexpr int GG = 1024;   // 4*H
constexpr int KIN = HH + EE;   // 556
constexpr int KAP = 576;       // KIN padded to 32-multiple
constexpr int MROWS = SS * BB; // 1984

// -------------------- device scratch (static, no allocs) --------------------
__device__ float  d_Xp[BB * HH];
__device__ float  d_xpart[16 * BB * HH];
__device__ __half d_Acat[MROWS * KAP];     // [Xp | emb | 0] fp16
__device__ float  d_bias2[GG];             // b_ih + b_hh
__device__ float  d_gpre[MROWS * GG];      // precomputed gate inputs (fp32)
__device__ __half d_Hall[MROWS * HH];      // h history fp16 (fc2 A matrix)
__device__ float  d_logits[MROWS * VV];
__device__ int    d_labels[TT * BB];
__device__ __half d_w2h[VV * HH];          // fc2_w fp16
__device__ __half d_wihh[GG * KAP];        // w_ih fp16, K-padded
__device__ unsigned bar_cnt4[4];
__device__ volatile unsigned bar_gen4[4];

// -------------------- helpers ------------------------------------------------
__device__ __forceinline__ void cp16(void* smem_dst, const void* gsrc, bool pred) {
    uint32_t saddr = (uint32_t)__cvta_generic_to_shared(smem_dst);
    int sz = pred ? 16 : 0;
    asm volatile("cp.async.cg.shared.global [%0], [%1], 16, %2;\n"
                 :: "r"(saddr), "l"(gsrc), "r"(sz) : "memory");
}
__device__ __forceinline__ void mma_f16(float* d, const uint32_t* a, const uint32_t* b) {
    asm volatile(
        "mma.sync.aligned.m16n8k16.row.col.f32.f16.f16.f32 "
        "{%0,%1,%2,%3}, {%4,%5,%6,%7}, {%8,%9}, {%0,%1,%2,%3};"
        : "+f"(d[0]), "+f"(d[1]), "+f"(d[2]), "+f"(d[3])
        : "r"(a[0]), "r"(a[1]), "r"(a[2]), "r"(a[3]), "r"(b[0]), "r"(b[1]));
}
__device__ __forceinline__ uint2 pack_h4(float4 v) {
    __half2 p0 = __floats2half2_rn(v.x, v.y);
    __half2 p1 = __floats2half2_rn(v.z, v.w);
    uint2 u;
    u.x = *(uint32_t*)&p0;
    u.y = *(uint32_t*)&p1;
    return u;
}
__device__ __forceinline__ float fast_tanh(float x) {
    float r;
    asm("tanh.approx.f32 %0, %1;" : "=f"(r) : "f"(x));
    return r;
}
__device__ __forceinline__ float fast_sigmoid(float x) {
    return 1.f / (1.f + __expf(-x));
}

// -------------------- fused prep: label decode + combined bias ---------------
__global__ void k_prep(const int* __restrict__ lab,
                       const float* __restrict__ bih,
                       const float* __restrict__ bhh) {
    __shared__ int is64;
    if (threadIdx.x == 0) {
        int f = 1;
        for (int i = 1; i < 64 && f; i += 2)
            if (lab[i] != 0) f = 0;
        is64 = f;
    }
    __syncthreads();
    for (int i = threadIdx.x; i < TT * BB; i += blockDim.x)
        d_labels[i] = is64 ? (int)(((const long long*)lab)[i]) : lab[i];
    for (int i = threadIdx.x; i < GG; i += blockDim.x)
        d_bias2[i] = bih[i] + bhh[i];
}

// -------------------- fc1: Xp = X @ fc1_w.T + b (split-K SIMT) ---------------
__global__ void __launch_bounds__(256) k_fc1(const float* __restrict__ X,
                                             const float* __restrict__ W) {
    const int h0 = blockIdx.x * 32;
    const int kb = blockIdx.y;
    const int kbase = kb * 256;
    const int tid = threadIdx.x;
    __shared__ __align__(16) float Xs[32][68];
    __shared__ float Wsh[32][33];
    float acc[4][2];
#pragma unroll
    for (int q = 0; q < 4; q++) { acc[q][0] = 0.f; acc[q][1] = 0.f; }
    const int tb = (tid & 15) * 4;
    const int th = (tid >> 4) * 2;

    for (int t = 0; t < 8; t++) {
        int k0 = kbase + t * 32;
#pragma unroll
        for (int i = 0; i < 8; i++) {
            int idx = tid + i * 256;
            int b = idx >> 5, kk = idx & 31;
            Xs[kk][b] = X[(size_t)b * FF + k0 + kk];
        }
#pragma unroll
        for (int i = 0; i < 4; i++) {
            int idx = tid + i * 256;
            int hh = idx >> 5, kk = idx & 31;
            Wsh[kk][hh] = W[(size_t)(h0 + hh) * FF + k0 + kk];
        }
        __syncthreads();
#pragma unroll
        for (int kk = 0; kk < 32; kk++) {
            float4 x4 = *(const float4*)&Xs[kk][tb];
            float w0 = Wsh[kk][th], w1 = Wsh[kk][th + 1];
            acc[0][0] += x4.x * w0; acc[0][1] += x4.x * w1;
            acc[1][0] += x4.y * w0; acc[1][1] += x4.y * w1;
            acc[2][0] += x4.z * w0; acc[2][1] += x4.z * w1;
            acc[3][0] += x4.w * w0; acc[3][1] += x4.w * w1;
        }
        __syncthreads();
    }
#pragma unroll
    for (int q = 0; q < 4; q++)
#pragma unroll
        for (int j = 0; j < 2; j++)
            d_xpart[kb * (BB * HH) + (tb + q) * HH + h0 + th + j] = acc[q][j];
}

__global__ void k_fc1red(const float* __restrict__ fc1_b) {
    int i4 = blockIdx.x * 256 + threadIdx.x;
    if (i4 < BB * HH / 4) {
        const float4* bp = (const float4*)fc1_b;
        float4 s = bp[i4 & 63];
#pragma unroll
        for (int kb = 0; kb < 16; kb++) {
            float4 p = ((const float4*)(d_xpart + kb * BB * HH))[i4];
            s.x += p.x; s.y += p.y; s.z += p.z; s.w += p.w;
        }
        ((float4*)d_Xp)[i4] = s;
    }
}

// -------------------- merged elementwise: buildA + wih cvt + fc2w cvt --------
constexpr int AC4 = KAP / 4;               // 144 groups per row
constexpr int R1 = MROWS * AC4;            // 285696
constexpr int R2 = GG * AC4;               // 147456
constexpr int R3 = VV * HH / 4;            // 640000
constexpr int RALL = R1 + R2 + R3;         // 1073152  (divisible by 256)
__global__ void __launch_bounds__(256) k_cvtall(const float* __restrict__ emb_table,
                                                const float* __restrict__ wih,
                                                const float* __restrict__ fc2w) {
    int idx = blockIdx.x * 256 + threadIdx.x;
    if (idx < R1) {                        // Acat = [Xp | emb | 0]
        int r = idx / AC4, c = idx - r * AC4;
        int s = r >> 6, b = r & 63;
        float4 v;
        if (c < 64) {
            v = ((const float4*)d_Xp)[b * 64 + c];
        } else if (c < 139) {
            int tok = (s == 0) ? 1 : d_labels[s * BB + b];   // START_ID = 1
            v = *(const float4*)(emb_table + (size_t)tok * EE + (c - 64) * 4);
        } else {
            v = make_float4(0.f, 0.f, 0.f, 0.f);
        }
        ((uint2*)d_Acat)[idx] = pack_h4(v);
    } else if (idx < R1 + R2) {            // w_ih -> fp16, K-padded
        int i = idx - R1;
        int r = i / AC4, c = i - r * AC4;
        float4 v = (c < 139) ? *(const float4*)(wih + (size_t)r * KIN + c * 4)
                             : make_float4(0.f, 0.f, 0.f, 0.f);
        ((uint2*)d_wihh)[i] = pack_h4(v);
    } else if (idx < RALL) {               // fc2_w -> fp16
        int i = idx - (R1 + R2);
        ((uint2*)d_w2h)[i] = pack_h4(((const float4*)fc2w)[i]);
    }
}

// -------------------- fp16 tensor-core GEMM (plain epilogue) -----------------
// C[M,N] = A[M,K] @ B[N,K]^T + bias[N]; 128x128 tile, BK=32, 8 warps,
// m16n8k16 f16 with f32 accumulate. K must be a multiple of 32.
__global__ void __launch_bounds__(256) k_hgemm(
    const __half* __restrict__ A, int lda,
    const __half* __restrict__ B, int ldb,
    const float* __restrict__ bias,
    float* __restrict__ C, int ldc,
    int M, int N, int K)
{
    __shared__ __align__(16) __half As[2][128][40];
    __shared__ __align__(16) __half Bs[2][128][40];

    const int tid = threadIdx.x;
    const int lane = tid & 31;
    const int warpId = tid >> 5;
    const int warpM = warpId & 3;
    const int warpN = warpId >> 2;
    const int g = lane >> 2;
    const int t = lane & 3;

    const int ncol = blockIdx.x * 128;
    const int mrow = blockIdx.y * 128;

    float acc[2][8][4];
#pragma unroll
    for (int mt = 0; mt < 2; mt++)
#pragma unroll
        for (int nt = 0; nt < 8; nt++)
#pragma unroll
            for (int q = 0; q < 4; q++) acc[mt][nt][q] = 0.f;

    const int NT = K >> 5;

    auto load_tile = [&](int buf, int kt) {
        int k0 = kt << 5;
#pragma unroll
        for (int i = 0; i < 2; i++) {
            int c = tid + i * 256;
            int m = c >> 2, kc = (c & 3) * 8;
            cp16(&As[buf][m][kc], A + (size_t)(mrow + m) * lda + k0 + kc,
                 (mrow + m) < M);
        }
#pragma unroll
        for (int i = 0; i < 2; i++) {
            int c = tid + i * 256;
            int n = c >> 2, kc = (c & 3) * 8;
            cp16(&Bs[buf][n][kc], B + (size_t)(ncol + n) * ldb + k0 + kc,
                 (ncol + n) < N);
        }
    };

    load_tile(0, 0);
    asm volatile("cp.async.commit_group;\n" ::: "memory");

    for (int kt = 0; kt < NT; kt++) {
        int buf = kt & 1;
        if (kt + 1 < NT) {
            load_tile(buf ^ 1, kt + 1);
            asm volatile("cp.async.commit_group;\n" ::: "memory");
            asm volatile("cp.async.wait_group 1;\n" ::: "memory");
        } else {
            asm volatile("cp.async.wait_group 0;\n" ::: "memory");
        }
        __syncthreads();

#pragma unroll
        for (int ks = 0; ks < 32; ks += 16) {
            uint32_t afr[2][4], bfr[8][2];
#pragma unroll
            for (int mt = 0; mt < 2; mt++) {
                int r0 = warpM * 32 + mt * 16;
                afr[mt][0] = *(const uint32_t*)&As[buf][r0 + g][ks + 2 * t];
                afr[mt][1] = *(const uint32_t*)&As[buf][r0 + g + 8][ks + 2 * t];
                afr[mt][2] = *(const uint32_t*)&As[buf][r0 + g][ks + 2 * t + 8];
                afr[mt][3] = *(const uint32_t*)&As[buf][r0 + g + 8][ks + 2 * t + 8];
            }
#pragma unroll
            for (int nt = 0; nt < 8; nt++) {
                int c0 = warpN * 64 + nt * 8;
                bfr[nt][0] = *(const uint32_t*)&Bs[buf][c0 + g][ks + 2 * t];
                bfr[nt][1] = *(const uint32_t*)&Bs[buf][c0 + g][ks + 2 * t + 8];
            }
#pragma unroll
            for (int mt = 0; mt < 2; mt++)
#pragma unroll
                for (int nt = 0; nt < 8; nt++)
                    mma_f16(acc[mt][nt], afr[mt], bfr[nt]);
        }
        __syncthreads();
    }

#pragma unroll
    for (int mt = 0; mt < 2; mt++) {
#pragma unroll
        for (int nt = 0; nt < 8; nt++) {
            int m0 = mrow + warpM * 32 + mt * 16 + g;
            int n0 = ncol + warpN * 64 + nt * 8 + 2 * t;
            if (n0 < N) {
                float b0 = bias[n0], b1 = bias[n0 + 1];
                if (m0 < M) {
                    C[(size_t)m0 * ldc + n0]     = acc[mt][nt][0] + b0;
                    C[(size_t)m0 * ldc + n0 + 1] = acc[mt][nt][1] + b1;
                }
                if (m0 + 8 < M) {
                    C[(size_t)(m0 + 8) * ldc + n0]     = acc[mt][nt][2] + b0;
                    C[(size_t)(m0 + 8) * ldc + n0 + 1] = acc[mt][nt][3] + b1;
                }
            }
        }
    }
}

// -------------------- recurrence: 4 batch-groups x 16 j-blocks ---------------
// Batch rows are independent through the scan; barrier is per-group (16 blocks,
// atomicInc + volatile generation flag — the configuration measured at 236us).
__global__ void __launch_bounds__(256, 1) k_rec(const float* __restrict__ w_hh) {
    __shared__ __align__(16) __half hs[16][264];   // h_prev (16 rows x 256)
    __shared__ float gbuf[16][68];                 // gate exchange

    const int tid = threadIdx.x;
    const int lane = tid & 31;
    const int wid = tid >> 5;
    const int g = lane >> 2;
    const int t = lane & 3;
    const int jb = blockIdx.x & 15;
    const int grp = blockIdx.x >> 4;
    const int j0 = jb * 16;
    const int brow0 = grp * 16;

    // preload w_hh fragments (fp16, 32 regs)
    uint32_t wb[16][2];
    {
        int lc = wid * 8 + g;                           // local col 0..63
        int wrow = (lc >> 4) * 256 + j0 + (lc & 15);    // gate*256 + j
        const float* wr = w_hh + (size_t)wrow * HH;
#pragma unroll
        for (int kt = 0; kt < 16; kt++) {
            __half2 h0 = __floats2half2_rn(wr[kt * 16 + 2 * t], wr[kt * 16 + 2 * t + 1]);
            __half2 h1 = __floats2half2_rn(wr[kt * 16 + 2 * t + 8], wr[kt * 16 + 2 * t + 9]);
            wb[kt][0] = *(uint32_t*)&h0;
            wb[kt][1] = *(uint32_t*)&h1;
        }
    }

    float creg = 0.f;
    const int cb = tid >> 4, cj = tid & 15;   // cell: 1 per thread
    const int lc = wid * 8 + 2 * t;
    const int r0 = (lc >> 4) * 256 + j0 + (lc & 15);
    unsigned mygen = bar_gen4[grp];

    for (int s = 0; s < SS; s++) {
        float acc[4] = {0.f, 0.f, 0.f, 0.f};

        // prefetch gpre (independent of h)
        const float* gp = d_gpre + ((size_t)s * BB + brow0) * GG;
        float2 g0 = *(const float2*)&gp[(size_t)g * GG + r0];
        float2 g1 = *(const float2*)&gp[(size_t)(g + 8) * GG + r0];

        if (s > 0) {
            const uint4* src = (const uint4*)(d_Hall + ((size_t)(s - 1) * BB + brow0) * HH);
#pragma unroll
            for (int i = 0; i < 2; i++) {
                int c = tid + i * 256;
                int m = c >> 5, kc = c & 31;
                *(uint4*)&hs[m][kc * 8] = src[m * 32 + kc];
            }
            __syncthreads();
#pragma unroll
            for (int kt = 0; kt < 16; kt++) {
                uint32_t af[4];
                af[0] = *(const uint32_t*)&hs[g][kt * 16 + 2 * t];
                af[1] = *(const uint32_t*)&hs[g + 8][kt * 16 + 2 * t];
                af[2] = *(const uint32_t*)&hs[g][kt * 16 + 2 * t + 8];
                af[3] = *(const uint32_t*)&hs[g + 8][kt * 16 + 2 * t + 8];
                mma_f16(acc, af, wb[kt]);
            }
        }

        gbuf[g][lc]         = acc[0] + g0.x;
        gbuf[g][lc + 1]     = acc[1] + g0.y;
        gbuf[g + 8][lc]     = acc[2] + g1.x;
        gbuf[g + 8][lc + 1] = acc[3] + g1.y;
        __syncthreads();

        {
            float gi = gbuf[cb][cj],      gf = gbuf[cb][16 + cj];
            float gc = gbuf[cb][32 + cj], go = gbuf[cb][48 + cj];
            float ii = fast_sigmoid(gi);
            float ff = fast_sigmoid(gf);
            float gv = fast_tanh(gc);
            float oo = fast_sigmoid(go);
            float cn = ff * creg + ii * gv;
            creg = cn;
            d_Hall[((size_t)s * BB + brow0 + cb) * HH + j0 + cj] =
                __float2half(oo * fast_tanh(cn));
        }

        if (s + 1 < SS) {
            __threadfence();
            __syncthreads();
            if (tid == 0) {
                if (atomicInc(&bar_cnt4[grp], 15) == 15) {
                    bar_gen4[grp] = mygen + 1;
                } else {
                    while (bar_gen4[grp] == mygen) {}
                }
            }
            __syncthreads();
            mygen++;
        }
    }
}

// -------------------- fused one-hot fill + online log-softmax ----------------
__global__ void __launch_bounds__(256) k_softmax(float* __restrict__ out) {
    const int r = blockIdx.x;
    const int tid = threadIdx.x;
    if (r >= MROWS) {                      // one-hot t=0 plane
        int b = r - MROWS;
        float* dst = out + (size_t)b * TT * VV;
        for (int v = tid; v < VV; v += 256) dst[v] = (v == 1) ? 1.f : 0.f;
        return;
    }
    const int s = r >> 6, b = r & 63;
    const float4* src = (const float4*)(d_logits + (size_t)r * VV);

    float m = -1e30f, sum = 0.f;
    for (int c = tid; c < VV / 4; c += 256) {
        float4 x = src[c];
        float m4 = fmaxf(fmaxf(x.x, x.y), fmaxf(x.z, x.w));
        if (m4 > m) { sum *= __expf(m - m4); m = m4; }
        sum += __expf(x.x - m) + __expf(x.y - m) + __expf(x.z - m) + __expf(x.w - m);
    }
#pragma unroll
    for (int o = 16; o; o >>= 1) {
        float mo = __shfl_xor_sync(0xffffffffu, m, o);
        float so = __shfl_xor_sync(0xffffffffu, sum, o);
        float M = fmaxf(m, mo);
        sum = sum * __expf(m - M) + so * __expf(mo - M);
        m = M;
    }
    __shared__ float sm_m[8], sm_s[8], s_lz;
    if ((tid & 31) == 0) { sm_m[tid >> 5] = m; sm_s[tid >> 5] = sum; }
    __syncthreads();
    if (tid == 0) {
        float M = sm_m[0], S = sm_s[0];
#pragma unroll
        for (int w = 1; w < 8; w++) {
            float mo = sm_m[w], so = sm_s[w];
            float MM = fmaxf(M, mo);
            S = S * __expf(M - MM) + so * __expf(mo - MM);
            M = MM;
        }
        s_lz = M + logf(S);
    }
    __syncthreads();
    float lz = s_lz;
    float4* dst = (float4*)(out + ((size_t)b * TT + s + 1) * VV);
    for (int c = tid; c < VV / 4; c += 256) {
        float4 x = src[c];
        x.x -= lz; x.y -= lz; x.z -= lz; x.w -= lz;
        dst[c] = x;
    }
}

// -------------------- launch ------------------------------------------------
extern "C" void kernel_launch(void* const* d_in, const int* in_sizes, int n_in,
                              void* d_out, int out_size) {
    const float* X    = (const float*)d_in[0];
    const float* emb  = (const float*)d_in[1];
    const float* fc1w = (const float*)d_in[2];
    const float* fc1b = (const float*)d_in[3];
    const float* wih  = (const float*)d_in[4];
    const float* whh  = (const float*)d_in[5];
    const float* bih  = (const float*)d_in[6];
    const float* bhh  = (const float*)d_in[7];
    const float* fc2w = (const float*)d_in[8];
    const float* fc2b = (const float*)d_in[9];
    const int*   lab  = (const int*)d_in[10];
    float* out = (float*)d_out;

    __half *pAcat, *pHall, *pW2h, *pWihh;
    float *pBias2, *pGpre, *pLogits;
    cudaGetSymbolAddress((void**)&pAcat,   d_Acat);
    cudaGetSymbolAddress((void**)&pBias2,  d_bias2);
    cudaGetSymbolAddress((void**)&pGpre,   d_gpre);
    cudaGetSymbolAddress((void**)&pHall,   d_Hall);
    cudaGetSymbolAddress((void**)&pLogits, d_logits);
    cudaGetSymbolAddress((void**)&pW2h,    d_w2h);
    cudaGetSymbolAddress((void**)&pWihh,   d_wihh);

    k_prep<<<1, 256>>>(lab, bih, bhh);
    k_fc1<<<dim3(8, 16), 256>>>(X, fc1w);
    k_fc1red<<<16, 256>>>(fc1b);
    k_cvtall<<<RALL / 256, 256>>>(emb, wih, fc2w);

    // gpre: [1984,1024] = Acat[1984,576] @ wihh[1024,576]^T + (bih+bhh)
    k_hgemm<<<dim3(8, 16), 256>>>(pAcat, KAP, pWihh, KAP, pBias2,
                                  pGpre, GG, MROWS, GG, KAP);

    // recurrence: 64 blocks = 4 batch-groups x 16 j-blocks
    k_rec<<<64, 256>>>(whh);

    // fc2: logits[1984,10000] = Hall @ w2h^T + fc2b
    k_hgemm<<<dim3(79, 16), 256>>>(pHall, HH, pW2h, HH, fc2b,
                                   pLogits, VV, MROWS, VV, HH);

    k_softmax<<<MROWS + BB, 256>>>(out);
}

// round 8
// speedup vs baseline: 1.3858x; 1.0668x over previous
#include <cuda_runtime.h>
#include <cuda_fp16.h>
#include <math.h>
#include <stdint.h>

// Problem dims
constexpr int BB = 64;
constexpr int TT = 32;
constexpr int SS = 31;     // scan steps (T-1)
constexpr int VV = 10000;
constexpr int EE = 300;
constexpr int HH = 256;
constexpr int FF = 4096;
constexpr int GG = 1024;   // 4*H
constexpr int KIN = HH + EE;   // 556
constexpr int KAP = 576;       // KIN padded to 32-multiple
constexpr int MROWS = SS * BB; // 1984

// -------------------- device scratch (static, no allocs) --------------------
__device__ float  d_Xp[BB * HH];
__device__ float  d_xpart[16 * BB * HH];
__device__ __half d_Acat[MROWS * KAP];     // [Xp | emb | 0] fp16
__device__ float  d_bias2[GG];             // b_ih + b_hh
__device__ float  d_gpre[MROWS * GG];      // precomputed gate inputs (fp32)
__device__ __half d_Hall[MROWS * HH];      // h history fp16 (fc2 A matrix)
__device__ __half d_logits[MROWS * VV];    // fc2 output, fp16 (40 MB)
__device__ int    d_labels[TT * BB];
__device__ __half d_w2h[VV * HH];          // fc2_w fp16
__device__ __half d_wihh[GG * KAP];        // w_ih fp16, K-padded
__device__ unsigned bar_cnt4[4];
__device__ volatile unsigned bar_gen4[4];

// -------------------- helpers ------------------------------------------------
__device__ __forceinline__ void cp16(void* smem_dst, const void* gsrc, bool pred) {
    uint32_t saddr = (uint32_t)__cvta_generic_to_shared(smem_dst);
    int sz = pred ? 16 : 0;
    asm volatile("cp.async.cg.shared.global [%0], [%1], 16, %2;\n"
                 :: "r"(saddr), "l"(gsrc), "r"(sz) : "memory");
}
__device__ __forceinline__ void mma_f16(float* d, const uint32_t* a, const uint32_t* b) {
    asm volatile(
        "mma.sync.aligned.m16n8k16.row.col.f32.f16.f16.f32 "
        "{%0,%1,%2,%3}, {%4,%5,%6,%7}, {%8,%9}, {%0,%1,%2,%3};"
        : "+f"(d[0]), "+f"(d[1]), "+f"(d[2]), "+f"(d[3])
        : "r"(a[0]), "r"(a[1]), "r"(a[2]), "r"(a[3]), "r"(b[0]), "r"(b[1]));
}
__device__ __forceinline__ uint2 pack_h4(float4 v) {
    __half2 p0 = __floats2half2_rn(v.x, v.y);
    __half2 p1 = __floats2half2_rn(v.z, v.w);
    uint2 u;
    u.x = *(uint32_t*)&p0;
    u.y = *(uint32_t*)&p1;
    return u;
}
__device__ __forceinline__ float fast_tanh(float x) {
    float r;
    asm("tanh.approx.f32 %0, %1;" : "=f"(r) : "f"(x));
    return r;
}
__device__ __forceinline__ float fast_sigmoid(float x) {
    return 1.f / (1.f + __expf(-x));
}

// -------------------- fused prep: label decode + combined bias ---------------
__global__ void k_prep(const int* __restrict__ lab,
                       const float* __restrict__ bih,
                       const float* __restrict__ bhh) {
    __shared__ int is64;
    if (threadIdx.x == 0) {
        int f = 1;
        for (int i = 1; i < 64 && f; i += 2)
            if (lab[i] != 0) f = 0;
        is64 = f;
    }
    __syncthreads();
    for (int i = threadIdx.x; i < TT * BB; i += blockDim.x)
        d_labels[i] = is64 ? (int)(((const long long*)lab)[i]) : lab[i];
    for (int i = threadIdx.x; i < GG; i += blockDim.x)
        d_bias2[i] = bih[i] + bhh[i];
}

// -------------------- fc1: Xp = X @ fc1_w.T + b (split-K SIMT) ---------------
__global__ void __launch_bounds__(256) k_fc1(const float* __restrict__ X,
                                             const float* __restrict__ W) {
    const int h0 = blockIdx.x * 32;
    const int kb = blockIdx.y;
    const int kbase = kb * 256;
    const int tid = threadIdx.x;
    __shared__ __align__(16) float Xs[32][68];
    __shared__ float Wsh[32][33];
    float acc[4][2];
#pragma unroll
    for (int q = 0; q < 4; q++) { acc[q][0] = 0.f; acc[q][1] = 0.f; }
    const int tb = (tid & 15) * 4;
    const int th = (tid >> 4) * 2;

    for (int t = 0; t < 8; t++) {
        int k0 = kbase + t * 32;
#pragma unroll
        for (int i = 0; i < 8; i++) {
            int idx = tid + i * 256;
            int b = idx >> 5, kk = idx & 31;
            Xs[kk][b] = X[(size_t)b * FF + k0 + kk];
        }
#pragma unroll
        for (int i = 0; i < 4; i++) {
            int idx = tid + i * 256;
            int hh = idx >> 5, kk = idx & 31;
            Wsh[kk][hh] = W[(size_t)(h0 + hh) * FF + k0 + kk];
        }
        __syncthreads();
#pragma unroll
        for (int kk = 0; kk < 32; kk++) {
            float4 x4 = *(const float4*)&Xs[kk][tb];
            float w0 = Wsh[kk][th], w1 = Wsh[kk][th + 1];
            acc[0][0] += x4.x * w0; acc[0][1] += x4.x * w1;
            acc[1][0] += x4.y * w0; acc[1][1] += x4.y * w1;
            acc[2][0] += x4.z * w0; acc[2][1] += x4.z * w1;
            acc[3][0] += x4.w * w0; acc[3][1] += x4.w * w1;
        }
        __syncthreads();
    }
#pragma unroll
    for (int q = 0; q < 4; q++)
#pragma unroll
        for (int j = 0; j < 2; j++)
            d_xpart[kb * (BB * HH) + (tb + q) * HH + h0 + th + j] = acc[q][j];
}

__global__ void k_fc1red(const float* __restrict__ fc1_b) {
    int i4 = blockIdx.x * 256 + threadIdx.x;
    if (i4 < BB * HH / 4) {
        const float4* bp = (const float4*)fc1_b;
        float4 s = bp[i4 & 63];
#pragma unroll
        for (int kb = 0; kb < 16; kb++) {
            float4 p = ((const float4*)(d_xpart + kb * BB * HH))[i4];
            s.x += p.x; s.y += p.y; s.z += p.z; s.w += p.w;
        }
        ((float4*)d_Xp)[i4] = s;
    }
}

// -------------------- merged elementwise: buildA + wih cvt + fc2w cvt --------
constexpr int AC4 = KAP / 4;               // 144 groups per row
constexpr int R1 = MROWS * AC4;            // 285696
constexpr int R2 = GG * AC4;               // 147456
constexpr int R3 = VV * HH / 4;            // 640000
constexpr int RALL = R1 + R2 + R3;         // 1073152  (divisible by 256)
__global__ void __launch_bounds__(256) k_cvtall(const float* __restrict__ emb_table,
                                                const float* __restrict__ wih,
                                                const float* __restrict__ fc2w) {
    int idx = blockIdx.x * 256 + threadIdx.x;
    if (idx < R1) {                        // Acat = [Xp | emb | 0]
        int r = idx / AC4, c = idx - r * AC4;
        int s = r >> 6, b = r & 63;
        float4 v;
        if (c < 64) {
            v = ((const float4*)d_Xp)[b * 64 + c];
        } else if (c < 139) {
            int tok = (s == 0) ? 1 : d_labels[s * BB + b];   // START_ID = 1
            v = *(const float4*)(emb_table + (size_t)tok * EE + (c - 64) * 4);
        } else {
            v = make_float4(0.f, 0.f, 0.f, 0.f);
        }
        ((uint2*)d_Acat)[idx] = pack_h4(v);
    } else if (idx < R1 + R2) {            // w_ih -> fp16, K-padded
        int i = idx - R1;
        int r = i / AC4, c = i - r * AC4;
        float4 v = (c < 139) ? *(const float4*)(wih + (size_t)r * KIN + c * 4)
                             : make_float4(0.f, 0.f, 0.f, 0.f);
        ((uint2*)d_wihh)[i] = pack_h4(v);
    } else if (idx < RALL) {               // fc2_w -> fp16
        int i = idx - (R1 + R2);
        ((uint2*)d_w2h)[i] = pack_h4(((const float4*)fc2w)[i]);
    }
}

// -------------------- fp16 tensor-core GEMM (templated output type) ----------
// C[M,N] = A[M,K] @ B[N,K]^T + bias[N]; 128x128 tile, BK=32, 8 warps,
// m16n8k16 f16 with f32 accumulate. OT = float (fp32 store) or __half (h2 store).
template <typename OT>
__global__ void __launch_bounds__(256) k_hgemm(
    const __half* __restrict__ A, int lda,
    const __half* __restrict__ B, int ldb,
    const float* __restrict__ bias,
    OT* __restrict__ C, int ldc,
    int M, int N, int K)
{
    __shared__ __align__(16) __half As[2][128][40];
    __shared__ __align__(16) __half Bs[2][128][40];

    const int tid = threadIdx.x;
    const int lane = tid & 31;
    const int warpId = tid >> 5;
    const int warpM = warpId & 3;
    const int warpN = warpId >> 2;
    const int g = lane >> 2;
    const int t = lane & 3;

    const int ncol = blockIdx.x * 128;
    const int mrow = blockIdx.y * 128;

    float acc[2][8][4];
#pragma unroll
    for (int mt = 0; mt < 2; mt++)
#pragma unroll
        for (int nt = 0; nt < 8; nt++)
#pragma unroll
            for (int q = 0; q < 4; q++) acc[mt][nt][q] = 0.f;

    const int NT = K >> 5;

    auto load_tile = [&](int buf, int kt) {
        int k0 = kt << 5;
#pragma unroll
        for (int i = 0; i < 2; i++) {
            int c = tid + i * 256;
            int m = c >> 2, kc = (c & 3) * 8;
            cp16(&As[buf][m][kc], A + (size_t)(mrow + m) * lda + k0 + kc,
                 (mrow + m) < M);
        }
#pragma unroll
        for (int i = 0; i < 2; i++) {
            int c = tid + i * 256;
            int n = c >> 2, kc = (c & 3) * 8;
            cp16(&Bs[buf][n][kc], B + (size_t)(ncol + n) * ldb + k0 + kc,
                 (ncol + n) < N);
        }
    };

    load_tile(0, 0);
    asm volatile("cp.async.commit_group;\n" ::: "memory");

    for (int kt = 0; kt < NT; kt++) {
        int buf = kt & 1;
        if (kt + 1 < NT) {
            load_tile(buf ^ 1, kt + 1);
            asm volatile("cp.async.commit_group;\n" ::: "memory");
            asm volatile("cp.async.wait_group 1;\n" ::: "memory");
        } else {
            asm volatile("cp.async.wait_group 0;\n" ::: "memory");
        }
        __syncthreads();

#pragma unroll
        for (int ks = 0; ks < 32; ks += 16) {
            uint32_t afr[2][4], bfr[8][2];
#pragma unroll
            for (int mt = 0; mt < 2; mt++) {
                int r0 = warpM * 32 + mt * 16;
                afr[mt][0] = *(const uint32_t*)&As[buf][r0 + g][ks + 2 * t];
                afr[mt][1] = *(const uint32_t*)&As[buf][r0 + g + 8][ks + 2 * t];
                afr[mt][2] = *(const uint32_t*)&As[buf][r0 + g][ks + 2 * t + 8];
                afr[mt][3] = *(const uint32_t*)&As[buf][r0 + g + 8][ks + 2 * t + 8];
            }
#pragma unroll
            for (int nt = 0; nt < 8; nt++) {
                int c0 = warpN * 64 + nt * 8;
                bfr[nt][0] = *(const uint32_t*)&Bs[buf][c0 + g][ks + 2 * t];
                bfr[nt][1] = *(const uint32_t*)&Bs[buf][c0 + g][ks + 2 * t + 8];
            }
#pragma unroll
            for (int mt = 0; mt < 2; mt++)
#pragma unroll
                for (int nt = 0; nt < 8; nt++)
                    mma_f16(acc[mt][nt], afr[mt], bfr[nt]);
        }
        __syncthreads();
    }

#pragma unroll
    for (int mt = 0; mt < 2; mt++) {
#pragma unroll
        for (int nt = 0; nt < 8; nt++) {
            int m0 = mrow + warpM * 32 + mt * 16 + g;
            int n0 = ncol + warpN * 64 + nt * 8 + 2 * t;
            if (n0 < N) {
                float b0 = bias[n0], b1 = bias[n0 + 1];
                float v0 = acc[mt][nt][0] + b0, v1 = acc[mt][nt][1] + b1;
                float v2 = acc[mt][nt][2] + b0, v3 = acc[mt][nt][3] + b1;
                if (sizeof(OT) == 4) {       // fp32 store
                    float* Cp = (float*)C;
                    if (m0 < M) {
                        Cp[(size_t)m0 * ldc + n0]     = v0;
                        Cp[(size_t)m0 * ldc + n0 + 1] = v1;
                    }
                    if (m0 + 8 < M) {
                        Cp[(size_t)(m0 + 8) * ldc + n0]     = v2;
                        Cp[(size_t)(m0 + 8) * ldc + n0 + 1] = v3;
                    }
                } else {                     // fp16 half2 store
                    __half* Cp = (__half*)C;
                    if (m0 < M) {
                        __half2 h01 = __floats2half2_rn(v0, v1);
                        *(uint32_t*)&Cp[(size_t)m0 * ldc + n0] = *(uint32_t*)&h01;
                    }
                    if (m0 + 8 < M) {
                        __half2 h23 = __floats2half2_rn(v2, v3);
                        *(uint32_t*)&Cp[(size_t)(m0 + 8) * ldc + n0] = *(uint32_t*)&h23;
                    }
                }
            }
        }
    }
}

// -------------------- recurrence: 4 batch-groups x 16 j-blocks ---------------
__global__ void __launch_bounds__(256, 1) k_rec(const float* __restrict__ w_hh) {
    __shared__ __align__(16) __half hs[16][264];   // h_prev (16 rows x 256)
    __shared__ float gbuf[16][68];                 // gate exchange

    const int tid = threadIdx.x;
    const int lane = tid & 31;
    const int wid = tid >> 5;
    const int g = lane >> 2;
    const int t = lane & 3;
    const int jb = blockIdx.x & 15;
    const int grp = blockIdx.x >> 4;
    const int j0 = jb * 16;
    const int brow0 = grp * 16;

    // preload w_hh fragments (fp16, 32 regs)
    uint32_t wb[16][2];
    {
        int lc = wid * 8 + g;                           // local col 0..63
        int wrow = (lc >> 4) * 256 + j0 + (lc & 15);    // gate*256 + j
        const float* wr = w_hh + (size_t)wrow * HH;
#pragma unroll
        for (int kt = 0; kt < 16; kt++) {
            __half2 h0 = __floats2half2_rn(wr[kt * 16 + 2 * t], wr[kt * 16 + 2 * t + 1]);
            __half2 h1 = __floats2half2_rn(wr[kt * 16 + 2 * t + 8], wr[kt * 16 + 2 * t + 9]);
            wb[kt][0] = *(uint32_t*)&h0;
            wb[kt][1] = *(uint32_t*)&h1;
        }
    }

    float creg = 0.f;
    const int cb = tid >> 4, cj = tid & 15;
    const int lc = wid * 8 + 2 * t;
    const int r0 = (lc >> 4) * 256 + j0 + (lc & 15);
    unsigned mygen = bar_gen4[grp];

    for (int s = 0; s < SS; s++) {
        float acc[4] = {0.f, 0.f, 0.f, 0.f};

        // prefetch gpre (independent of h)
        const float* gp = d_gpre + ((size_t)s * BB + brow0) * GG;
        float2 g0 = *(const float2*)&gp[(size_t)g * GG + r0];
        float2 g1 = *(const float2*)&gp[(size_t)(g + 8) * GG + r0];

        if (s > 0) {
            const uint4* src = (const uint4*)(d_Hall + ((size_t)(s - 1) * BB + brow0) * HH);
#pragma unroll
            for (int i = 0; i < 2; i++) {
                int c = tid + i * 256;
                int m = c >> 5, kc = c & 31;
                *(uint4*)&hs[m][kc * 8] = src[m * 32 + kc];
            }
            __syncthreads();
#pragma unroll
            for (int kt = 0; kt < 16; kt++) {
                uint32_t af[4];
                af[0] = *(const uint32_t*)&hs[g][kt * 16 + 2 * t];
                af[1] = *(const uint32_t*)&hs[g + 8][kt * 16 + 2 * t];
                af[2] = *(const uint32_t*)&hs[g][kt * 16 + 2 * t + 8];
                af[3] = *(const uint32_t*)&hs[g + 8][kt * 16 + 2 * t + 8];
                mma_f16(acc, af, wb[kt]);
            }
        }

        gbuf[g][lc]         = acc[0] + g0.x;
        gbuf[g][lc + 1]     = acc[1] + g0.y;
        gbuf[g + 8][lc]     = acc[2] + g1.x;
        gbuf[g + 8][lc + 1] = acc[3] + g1.y;
        __syncthreads();

        {
            float gi = gbuf[cb][cj],      gf = gbuf[cb][16 + cj];
            float gc = gbuf[cb][32 + cj], go = gbuf[cb][48 + cj];
            float ii = fast_sigmoid(gi);
            float ff = fast_sigmoid(gf);
            float gv = fast_tanh(gc);
            float oo = fast_sigmoid(go);
            float cn = ff * creg + ii * gv;
            creg = cn;
            d_Hall[((size_t)s * BB + brow0 + cb) * HH + j0 + cj] =
                __float2half(oo * fast_tanh(cn));
        }

        if (s + 1 < SS) {
            __threadfence();
            __syncthreads();
            if (tid == 0) {
                if (atomicInc(&bar_cnt4[grp], 15) == 15) {
                    bar_gen4[grp] = mygen + 1;
                } else {
                    while (bar_gen4[grp] == mygen) {}
                }
            }
            __syncthreads();
            mygen++;
        }
    }
}

// -------------------- fused one-hot + log-softmax (register-cached row) ------
// Row = 10000 fp16 = 1250 uint4; 256 threads x 5 uint4 covers it. Logits are
// read from DRAM exactly once; pass 2 works from registers.
constexpr int V8 = VV / 8;   // 1250 uint4 groups
__global__ void __launch_bounds__(256) k_softmax(float* __restrict__ out) {
    const int r = blockIdx.x;
    const int tid = threadIdx.x;
    if (r >= MROWS) {                      // one-hot t=0 plane
        int b = r - MROWS;
        float* dst = out + (size_t)b * TT * VV;
        for (int v = tid; v < VV; v += 256) dst[v] = (v == 1) ? 1.f : 0.f;
        return;
    }
    const int s = r >> 6, b = r & 63;
    const uint4* src = (const uint4*)(d_logits + (size_t)r * VV);

    uint4 vals[5];
    float m = -1e30f, sum = 0.f;
#pragma unroll
    for (int i = 0; i < 5; i++) {
        int c = tid + i * 256;
        if (c < V8) {
            uint4 u = src[c];
            vals[i] = u;
            float2 f0 = __half22float2(*(__half2*)&u.x);
            float2 f1 = __half22float2(*(__half2*)&u.y);
            float2 f2 = __half22float2(*(__half2*)&u.z);
            float2 f3 = __half22float2(*(__half2*)&u.w);
            float m8 = fmaxf(fmaxf(fmaxf(f0.x, f0.y), fmaxf(f1.x, f1.y)),
                             fmaxf(fmaxf(f2.x, f2.y), fmaxf(f3.x, f3.y)));
            if (m8 > m) { sum *= __expf(m - m8); m = m8; }
            sum += __expf(f0.x - m) + __expf(f0.y - m)
                 + __expf(f1.x - m) + __expf(f1.y - m)
                 + __expf(f2.x - m) + __expf(f2.y - m)
                 + __expf(f3.x - m) + __expf(f3.y - m);
        }
    }
#pragma unroll
    for (int o = 16; o; o >>= 1) {
        float mo = __shfl_xor_sync(0xffffffffu, m, o);
        float so = __shfl_xor_sync(0xffffffffu, sum, o);
        float M = fmaxf(m, mo);
        sum = sum * __expf(m - M) + so * __expf(mo - M);
        m = M;
    }
    __shared__ float sm_m[8], sm_s[8], s_lz;
    if ((tid & 31) == 0) { sm_m[tid >> 5] = m; sm_s[tid >> 5] = sum; }
    __syncthreads();
    if (tid == 0) {
        float M = sm_m[0], S = sm_s[0];
#pragma unroll
        for (int w = 1; w < 8; w++) {
            float mo = sm_m[w], so = sm_s[w];
            float MM = fmaxf(M, mo);
            S = S * __expf(M - MM) + so * __expf(mo - MM);
            M = MM;
        }
        s_lz = M + logf(S);
    }
    __syncthreads();
    const float lz = s_lz;
    float4* dst = (float4*)(out + ((size_t)b * TT + s + 1) * VV);
#pragma unroll
    for (int i = 0; i < 5; i++) {
        int c = tid + i * 256;
        if (c < V8) {
            uint4 u = vals[i];
            float2 f0 = __half22float2(*(__half2*)&u.x);
            float2 f1 = __half22float2(*(__half2*)&u.y);
            float2 f2 = __half22float2(*(__half2*)&u.z);
            float2 f3 = __half22float2(*(__half2*)&u.w);
            dst[2 * c]     = make_float4(f0.x - lz, f0.y - lz, f1.x - lz, f1.y - lz);
            dst[2 * c + 1] = make_float4(f2.x - lz, f2.y - lz, f3.x - lz, f3.y - lz);
        }
    }
}

// -------------------- launch ------------------------------------------------
extern "C" void kernel_launch(void* const* d_in, const int* in_sizes, int n_in,
                              void* d_out, int out_size) {
    const float* X    = (const float*)d_in[0];
    const float* emb  = (const float*)d_in[1];
    const float* fc1w = (const float*)d_in[2];
    const float* fc1b = (const float*)d_in[3];
    const float* wih  = (const float*)d_in[4];
    const float* whh  = (const float*)d_in[5];
    const float* bih  = (const float*)d_in[6];
    const float* bhh  = (const float*)d_in[7];
    const float* fc2w = (const float*)d_in[8];
    const float* fc2b = (const float*)d_in[9];
    const int*   lab  = (const int*)d_in[10];
    float* out = (float*)d_out;

    __half *pAcat, *pHall, *pW2h, *pWihh, *pLogits;
    float *pBias2, *pGpre;
    cudaGetSymbolAddress((void**)&pAcat,   d_Acat);
    cudaGetSymbolAddress((void**)&pBias2,  d_bias2);
    cudaGetSymbolAddress((void**)&pGpre,   d_gpre);
    cudaGetSymbolAddress((void**)&pHall,   d_Hall);
    cudaGetSymbolAddress((void**)&pLogits, d_logits);
    cudaGetSymbolAddress((void**)&pW2h,    d_w2h);
    cudaGetSymbolAddress((void**)&pWihh,   d_wihh);

    k_prep<<<1, 256>>>(lab, bih, bhh);
    k_fc1<<<dim3(8, 16), 256>>>(X, fc1w);
    k_fc1red<<<16, 256>>>(fc1b);
    k_cvtall<<<RALL / 256, 256>>>(emb, wih, fc2w);

    // gpre: [1984,1024] = Acat[1984,576] @ wihh[1024,576]^T + (bih+bhh)
    k_hgemm<float><<<dim3(8, 16), 256>>>(pAcat, KAP, pWihh, KAP, pBias2,
                                         pGpre, GG, MROWS, GG, KAP);

    // recurrence: 64 blocks = 4 batch-groups x 16 j-blocks
    k_rec<<<64, 256>>>(whh);

    // fc2: logits[1984,10000] (fp16) = Hall @ w2h^T + fc2b
    k_hgemm<__half><<<dim3(79, 16), 256>>>(pHall, HH, pW2h, HH, fc2b,
                                           pLogits, VV, MROWS, VV, HH);

    k_softmax<<<MROWS + BB, 256>>>(out);
}

// round 9
// speedup vs baseline: 1.5477x; 1.1168x over previous
#include <cuda_runtime.h>
#include <cuda_fp16.h>
#include <math.h>
#include <stdint.h>

// Problem dims
constexpr int BB = 64;
constexpr int TT = 32;
constexpr int SS = 31;     // scan steps (T-1)
constexpr int VV = 10000;
constexpr int EE = 300;
constexpr int HH = 256;
constexpr int FF = 4096;
constexpr int GG = 1024;   // 4*H
constexpr int KIN = HH + EE;   // 556
constexpr int KAP = 576;       // KIN padded to 32-multiple
constexpr int MROWS = SS * BB; // 1984

// -------------------- device scratch (static, no allocs) --------------------
__device__ float  d_Xp[BB * HH];
__device__ float  d_xpart[16 * BB * HH];
__device__ __half d_Acat[MROWS * KAP];     // [Xp | emb | 0] fp16
__device__ float  d_bias2[GG];             // b_ih + b_hh
__device__ float  d_gpre[MROWS * GG];      // precomputed gate inputs (fp32)
__device__ __half d_Hall[MROWS * HH];      // h history fp16 (fc2 A matrix)
__device__ __half d_logits[MROWS * VV];    // fc2 output, fp16 (40 MB)
__device__ int    d_labels[TT * BB];
__device__ __half d_w2h[VV * HH];          // fc2_w fp16
__device__ __half d_wihh[GG * KAP];        // w_ih fp16, K-padded

// -------------------- helpers ------------------------------------------------
__device__ __forceinline__ void cp16(void* smem_dst, const void* gsrc, bool pred) {
    uint32_t saddr = (uint32_t)__cvta_generic_to_shared(smem_dst);
    int sz = pred ? 16 : 0;
    asm volatile("cp.async.cg.shared.global [%0], [%1], 16, %2;\n"
                 :: "r"(saddr), "l"(gsrc), "r"(sz) : "memory");
}
__device__ __forceinline__ void mma_f16(float* d, const uint32_t* a, const uint32_t* b) {
    asm volatile(
        "mma.sync.aligned.m16n8k16.row.col.f32.f16.f16.f32 "
        "{%0,%1,%2,%3}, {%4,%5,%6,%7}, {%8,%9}, {%0,%1,%2,%3};"
        : "+f"(d[0]), "+f"(d[1]), "+f"(d[2]), "+f"(d[3])
        : "r"(a[0]), "r"(a[1]), "r"(a[2]), "r"(a[3]), "r"(b[0]), "r"(b[1]));
}
__device__ __forceinline__ uint2 pack_h4(float4 v) {
    __half2 p0 = __floats2half2_rn(v.x, v.y);
    __half2 p1 = __floats2half2_rn(v.z, v.w);
    uint2 u;
    u.x = *(uint32_t*)&p0;
    u.y = *(uint32_t*)&p1;
    return u;
}
__device__ __forceinline__ float fast_tanh(float x) {
    float r;
    asm("tanh.approx.f32 %0, %1;" : "=f"(r) : "f"(x));
    return r;
}
__device__ __forceinline__ float fast_sigmoid(float x) {
    return 1.f / (1.f + __expf(-x));
}

// -------------------- fc1: Xp = X @ fc1_w.T + b (split-K SIMT) ---------------
__global__ void __launch_bounds__(256) k_fc1(const float* __restrict__ X,
                                             const float* __restrict__ W) {
    const int h0 = blockIdx.x * 32;
    const int kb = blockIdx.y;
    const int kbase = kb * 256;
    const int tid = threadIdx.x;
    __shared__ __align__(16) float Xs[32][68];
    __shared__ float Wsh[32][33];
    float acc[4][2];
#pragma unroll
    for (int q = 0; q < 4; q++) { acc[q][0] = 0.f; acc[q][1] = 0.f; }
    const int tb = (tid & 15) * 4;
    const int th = (tid >> 4) * 2;

    for (int t = 0; t < 8; t++) {
        int k0 = kbase + t * 32;
#pragma unroll
        for (int i = 0; i < 8; i++) {
            int idx = tid + i * 256;
            int b = idx >> 5, kk = idx & 31;
            Xs[kk][b] = X[(size_t)b * FF + k0 + kk];
        }
#pragma unroll
        for (int i = 0; i < 4; i++) {
            int idx = tid + i * 256;
            int hh = idx >> 5, kk = idx & 31;
            Wsh[kk][hh] = W[(size_t)(h0 + hh) * FF + k0 + kk];
        }
        __syncthreads();
#pragma unroll
        for (int kk = 0; kk < 32; kk++) {
            float4 x4 = *(const float4*)&Xs[kk][tb];
            float w0 = Wsh[kk][th], w1 = Wsh[kk][th + 1];
            acc[0][0] += x4.x * w0; acc[0][1] += x4.x * w1;
            acc[1][0] += x4.y * w0; acc[1][1] += x4.y * w1;
            acc[2][0] += x4.z * w0; acc[2][1] += x4.z * w1;
            acc[3][0] += x4.w * w0; acc[3][1] += x4.w * w1;
        }
        __syncthreads();
    }
#pragma unroll
    for (int q = 0; q < 4; q++)
#pragma unroll
        for (int j = 0; j < 2; j++)
            d_xpart[kb * (BB * HH) + (tb + q) * HH + h0 + th + j] = acc[q][j];
}

// -------------------- fc1 reduce + fused prep (blocks 16/17) -----------------
__global__ void k_fc1red(const float* __restrict__ fc1_b,
                         const int* __restrict__ lab,
                         const float* __restrict__ bih,
                         const float* __restrict__ bhh) {
    const int blk = blockIdx.x;
    const int tid = threadIdx.x;
    if (blk < 16) {
        int i4 = blk * 256 + tid;
        const float4* bp = (const float4*)fc1_b;
        float4 s = bp[i4 & 63];
#pragma unroll
        for (int kb = 0; kb < 16; kb++) {
            float4 p = ((const float4*)(d_xpart + kb * BB * HH))[i4];
            s.x += p.x; s.y += p.y; s.z += p.z; s.w += p.w;
        }
        ((float4*)d_Xp)[i4] = s;
    } else if (blk == 16) {
        __shared__ int is64;
        if (tid == 0) {
            int f = 1;
            for (int i = 1; i < 64 && f; i += 2)
                if (lab[i] != 0) f = 0;
            is64 = f;
        }
        __syncthreads();
        for (int i = tid; i < TT * BB; i += 256)
            d_labels[i] = is64 ? (int)(((const long long*)lab)[i]) : lab[i];
    } else {
        for (int i = tid; i < GG; i += 256)
            d_bias2[i] = bih[i] + bhh[i];
    }
}

// -------------------- merged elementwise: buildA + wih cvt + fc2w cvt --------
constexpr int AC4 = KAP / 4;               // 144 groups per row
constexpr int R1 = MROWS * AC4;            // 285696
constexpr int R2 = GG * AC4;               // 147456
constexpr int R3 = VV * HH / 4;            // 640000
constexpr int RALL = R1 + R2 + R3;         // 1073152  (divisible by 256)
__global__ void __launch_bounds__(256) k_cvtall(const float* __restrict__ emb_table,
                                                const float* __restrict__ wih,
                                                const float* __restrict__ fc2w) {
    int idx = blockIdx.x * 256 + threadIdx.x;
    if (idx < R1) {                        // Acat = [Xp | emb | 0]
        int r = idx / AC4, c = idx - r * AC4;
        int s = r >> 6, b = r & 63;
        float4 v;
        if (c < 64) {
            v = ((const float4*)d_Xp)[b * 64 + c];
        } else if (c < 139) {
            int tok = (s == 0) ? 1 : d_labels[s * BB + b];   // START_ID = 1
            v = *(const float4*)(emb_table + (size_t)tok * EE + (c - 64) * 4);
        } else {
            v = make_float4(0.f, 0.f, 0.f, 0.f);
        }
        ((uint2*)d_Acat)[idx] = pack_h4(v);
    } else if (idx < R1 + R2) {            // w_ih -> fp16, K-padded
        int i = idx - R1;
        int r = i / AC4, c = i - r * AC4;
        float4 v = (c < 139) ? *(const float4*)(wih + (size_t)r * KIN + c * 4)
                             : make_float4(0.f, 0.f, 0.f, 0.f);
        ((uint2*)d_wihh)[i] = pack_h4(v);
    } else if (idx < RALL) {               // fc2_w -> fp16
        int i = idx - (R1 + R2);
        ((uint2*)d_w2h)[i] = pack_h4(((const float4*)fc2w)[i]);
    }
}

// -------------------- fp16 tensor-core GEMM (templated output type) ----------
template <typename OT>
__global__ void __launch_bounds__(256) k_hgemm(
    const __half* __restrict__ A, int lda,
    const __half* __restrict__ B, int ldb,
    const float* __restrict__ bias,
    OT* __restrict__ C, int ldc,
    int M, int N, int K)
{
    __shared__ __align__(16) __half As[2][128][40];
    __shared__ __align__(16) __half Bs[2][128][40];

    const int tid = threadIdx.x;
    const int lane = tid & 31;
    const int warpId = tid >> 5;
    const int warpM = warpId & 3;
    const int warpN = warpId >> 2;
    const int g = lane >> 2;
    const int t = lane & 3;

    const int ncol = blockIdx.x * 128;
    const int mrow = blockIdx.y * 128;

    float acc[2][8][4];
#pragma unroll
    for (int mt = 0; mt < 2; mt++)
#pragma unroll
        for (int nt = 0; nt < 8; nt++)
#pragma unroll
            for (int q = 0; q < 4; q++) acc[mt][nt][q] = 0.f;

    const int NT = K >> 5;

    auto load_tile = [&](int buf, int kt) {
        int k0 = kt << 5;
#pragma unroll
        for (int i = 0; i < 2; i++) {
            int c = tid + i * 256;
            int m = c >> 2, kc = (c & 3) * 8;
            cp16(&As[buf][m][kc], A + (size_t)(mrow + m) * lda + k0 + kc,
                 (mrow + m) < M);
        }
#pragma unroll
        for (int i = 0; i < 2; i++) {
            int c = tid + i * 256;
            int n = c >> 2, kc = (c & 3) * 8;
            cp16(&Bs[buf][n][kc], B + (size_t)(ncol + n) * ldb + k0 + kc,
                 (ncol + n) < N);
        }
    };

    load_tile(0, 0);
    asm volatile("cp.async.commit_group;\n" ::: "memory");

    for (int kt = 0; kt < NT; kt++) {
        int buf = kt & 1;
        if (kt + 1 < NT) {
            load_tile(buf ^ 1, kt + 1);
            asm volatile("cp.async.commit_group;\n" ::: "memory");
            asm volatile("cp.async.wait_group 1;\n" ::: "memory");
        } else {
            asm volatile("cp.async.wait_group 0;\n" ::: "memory");
        }
        __syncthreads();

#pragma unroll
        for (int ks = 0; ks < 32; ks += 16) {
            uint32_t afr[2][4], bfr[8][2];
#pragma unroll
            for (int mt = 0; mt < 2; mt++) {
                int r0 = warpM * 32 + mt * 16;
                afr[mt][0] = *(const uint32_t*)&As[buf][r0 + g][ks + 2 * t];
                afr[mt][1] = *(const uint32_t*)&As[buf][r0 + g + 8][ks + 2 * t];
                afr[mt][2] = *(const uint32_t*)&As[buf][r0 + g][ks + 2 * t + 8];
                afr[mt][3] = *(const uint32_t*)&As[buf][r0 + g + 8][ks + 2 * t + 8];
            }
#pragma unroll
            for (int nt = 0; nt < 8; nt++) {
                int c0 = warpN * 64 + nt * 8;
                bfr[nt][0] = *(const uint32_t*)&Bs[buf][c0 + g][ks + 2 * t];
                bfr[nt][1] = *(const uint32_t*)&Bs[buf][c0 + g][ks + 2 * t + 8];
            }
#pragma unroll
            for (int mt = 0; mt < 2; mt++)
#pragma unroll
                for (int nt = 0; nt < 8; nt++)
                    mma_f16(acc[mt][nt], afr[mt], bfr[nt]);
        }
        __syncthreads();
    }

#pragma unroll
    for (int mt = 0; mt < 2; mt++) {
#pragma unroll
        for (int nt = 0; nt < 8; nt++) {
            int m0 = mrow + warpM * 32 + mt * 16 + g;
            int n0 = ncol + warpN * 64 + nt * 8 + 2 * t;
            if (n0 < N) {
                float b0 = bias[n0], b1 = bias[n0 + 1];
                float v0 = acc[mt][nt][0] + b0, v1 = acc[mt][nt][1] + b1;
                float v2 = acc[mt][nt][2] + b0, v3 = acc[mt][nt][3] + b1;
                if (sizeof(OT) == 4) {       // fp32 store
                    float* Cp = (float*)C;
                    if (m0 < M) {
                        Cp[(size_t)m0 * ldc + n0]     = v0;
                        Cp[(size_t)m0 * ldc + n0 + 1] = v1;
                    }
                    if (m0 + 8 < M) {
                        Cp[(size_t)(m0 + 8) * ldc + n0]     = v2;
                        Cp[(size_t)(m0 + 8) * ldc + n0 + 1] = v3;
                    }
                } else {                     // fp16 half2 store
                    __half* Cp = (__half*)C;
                    if (m0 < M) {
                        __half2 h01 = __floats2half2_rn(v0, v1);
                        *(uint32_t*)&Cp[(size_t)m0 * ldc + n0] = *(uint32_t*)&h01;
                    }
                    if (m0 + 8 < M) {
                        __half2 h23 = __floats2half2_rn(v2, v3);
                        *(uint32_t*)&Cp[(size_t)(m0 + 8) * ldc + n0] = *(uint32_t*)&h23;
                    }
                }
            }
        }
    }
}

// -------------------- recurrence: 4 clusters x 8 CTAs ------------------------
// Cluster = one batch-group (16 rows); each CTA owns 32 j-cols (128 gate cols).
// Inter-step sync = barrier.cluster (arrive=release, wait=acquire at cluster
// scope — covers the d_Hall global stores). No fences, no atomics, no spin.
// w_hh fragments register-resident (64 regs); two accumulators halve the HMMA
// dependency chain.
__global__ void __launch_bounds__(256, 1) __cluster_dims__(8, 1, 1)
k_rec(const float* __restrict__ w_hh) {
    __shared__ __align__(16) __half hs[16][264];   // h_prev (16 rows x 256)
    __shared__ float gbuf[16][132];                // gate exchange (128 cols)

    const int tid = threadIdx.x;
    const int lane = tid & 31;
    const int wid = tid >> 5;
    const int g = lane >> 2;
    const int t = lane & 3;
    const int rank = blockIdx.x & 7;
    const int grp = blockIdx.x >> 3;
    const int j0 = rank * 32;
    const int brow0 = grp * 16;

    // preload w_hh fragments: 2 n-frags x 16 kt x 2 regs = 64 regs
    uint32_t wb[2][16][2];
#pragma unroll
    for (int nt = 0; nt < 2; nt++) {
        int lc = wid * 16 + nt * 8 + g;                 // local col 0..127
        int wrow = (lc >> 5) * 256 + j0 + (lc & 31);    // gate*256 + j
        const float* wr = w_hh + (size_t)wrow * HH;
#pragma unroll
        for (int kt = 0; kt < 16; kt++) {
            __half2 h0 = __floats2half2_rn(wr[kt * 16 + 2 * t], wr[kt * 16 + 2 * t + 1]);
            __half2 h1 = __floats2half2_rn(wr[kt * 16 + 2 * t + 8], wr[kt * 16 + 2 * t + 9]);
            wb[nt][kt][0] = *(uint32_t*)&h0;
            wb[nt][kt][1] = *(uint32_t*)&h1;
        }
    }

    float creg[2] = {0.f, 0.f};
    const int crow = tid >> 4;          // cell row 0..15
    const int cj2 = (tid & 15) * 2;     // local j base (2 cells/thread)
    // epilogue column bases
    int lc0[2], r0[2];
#pragma unroll
    for (int nt = 0; nt < 2; nt++) {
        lc0[nt] = wid * 16 + nt * 8 + 2 * t;
        r0[nt] = (lc0[nt] >> 5) * 256 + j0 + (lc0[nt] & 31);
    }

    for (int s = 0; s < SS; s++) {
        // prefetch gpre (independent of h)
        const float* gp = d_gpre + ((size_t)s * BB + brow0) * GG;
        float2 q0[2], q1[2];
#pragma unroll
        for (int nt = 0; nt < 2; nt++) {
            q0[nt] = *(const float2*)&gp[(size_t)g * GG + r0[nt]];
            q1[nt] = *(const float2*)&gp[(size_t)(g + 8) * GG + r0[nt]];
        }

        float accA[2][4] = {{0.f, 0.f, 0.f, 0.f}, {0.f, 0.f, 0.f, 0.f}};
        float accB[2][4] = {{0.f, 0.f, 0.f, 0.f}, {0.f, 0.f, 0.f, 0.f}};

        if (s > 0) {
            const uint4* src = (const uint4*)(d_Hall + ((size_t)(s - 1) * BB + brow0) * HH);
#pragma unroll
            for (int i = 0; i < 2; i++) {
                int c = tid + i * 256;
                int m = c >> 5, kc = c & 31;
                *(uint4*)&hs[m][kc * 8] = src[m * 32 + kc];
            }
            __syncthreads();
#pragma unroll
            for (int kt = 0; kt < 16; kt++) {
                uint32_t af[4];
                af[0] = *(const uint32_t*)&hs[g][kt * 16 + 2 * t];
                af[1] = *(const uint32_t*)&hs[g + 8][kt * 16 + 2 * t];
                af[2] = *(const uint32_t*)&hs[g][kt * 16 + 2 * t + 8];
                af[3] = *(const uint32_t*)&hs[g + 8][kt * 16 + 2 * t + 8];
                float* d0 = (kt < 8) ? accA[0] : accB[0];
                float* d1 = (kt < 8) ? accA[1] : accB[1];
                mma_f16(d0, af, wb[0][kt]);
                mma_f16(d1, af, wb[1][kt]);
            }
        }

        // gates = acc + gpre -> gbuf
#pragma unroll
        for (int nt = 0; nt < 2; nt++) {
            gbuf[g][lc0[nt]]         = accA[nt][0] + accB[nt][0] + q0[nt].x;
            gbuf[g][lc0[nt] + 1]     = accA[nt][1] + accB[nt][1] + q0[nt].y;
            gbuf[g + 8][lc0[nt]]     = accA[nt][2] + accB[nt][2] + q1[nt].x;
            gbuf[g + 8][lc0[nt] + 1] = accA[nt][3] + accB[nt][3] + q1[nt].y;
        }
        __syncthreads();

        // LSTM cell: 2 cells per thread, store packed fp16 h
        {
            float hv[2];
#pragma unroll
            for (int e = 0; e < 2; e++) {
                int jj = cj2 + e;
                float gi = gbuf[crow][jj],      gf = gbuf[crow][32 + jj];
                float gc = gbuf[crow][64 + jj], go = gbuf[crow][96 + jj];
                float ii = fast_sigmoid(gi);
                float ff = fast_sigmoid(gf);
                float gv = fast_tanh(gc);
                float oo = fast_sigmoid(go);
                float cn = ff * creg[e] + ii * gv;
                creg[e] = cn;
                hv[e] = oo * fast_tanh(cn);
            }
            __half2 hp = __floats2half2_rn(hv[0], hv[1]);
            *(uint32_t*)&d_Hall[((size_t)s * BB + brow0 + crow) * HH + j0 + cj2] =
                *(uint32_t*)&hp;
        }

        if (s + 1 < SS) {
            asm volatile("barrier.cluster.arrive.aligned;" ::: "memory");
            asm volatile("barrier.cluster.wait.aligned;" ::: "memory");
        }
    }
}

// -------------------- fused one-hot + log-softmax (register-cached row) ------
constexpr int V8 = VV / 8;   // 1250 uint4 groups
__global__ void __launch_bounds__(256) k_softmax(float* __restrict__ out) {
    const int r = blockIdx.x;
    const int tid = threadIdx.x;
    if (r >= MROWS) {                      // one-hot t=0 plane
        int b = r - MROWS;
        float* dst = out + (size_t)b * TT * VV;
        for (int v = tid * 4; v < VV; v += 1024) {
            float4 z = make_float4(v == 0 ? 0.f : (v == 0 ? 1.f : 0.f), 0.f, 0.f, 0.f);
            z.x = 0.f; z.y = 0.f; z.z = 0.f; z.w = 0.f;
            if (v <= 1 && v + 1 >= 1) z.y = 1.f;   // index 1 = START_ID
            __stcs((float4*)(dst + v), z);
        }
        return;
    }
    const int s = r >> 6, b = r & 63;
    const uint4* src = (const uint4*)(d_logits + (size_t)r * VV);

    uint4 vals[5];
    float m = -1e30f, sum = 0.f;
#pragma unroll
    for (int i = 0; i < 5; i++) {
        int c = tid + i * 256;
        if (c < V8) {
            uint4 u = src[c];
            vals[i] = u;
            float2 f0 = __half22float2(*(__half2*)&u.x);
            float2 f1 = __half22float2(*(__half2*)&u.y);
            float2 f2 = __half22float2(*(__half2*)&u.z);
            float2 f3 = __half22float2(*(__half2*)&u.w);
            float m8 = fmaxf(fmaxf(fmaxf(f0.x, f0.y), fmaxf(f1.x, f1.y)),
                             fmaxf(fmaxf(f2.x, f2.y), fmaxf(f3.x, f3.y)));
            if (m8 > m) { sum *= __expf(m - m8); m = m8; }
            sum += __expf(f0.x - m) + __expf(f0.y - m)
                 + __expf(f1.x - m) + __expf(f1.y - m)
                 + __expf(f2.x - m) + __expf(f2.y - m)
                 + __expf(f3.x - m) + __expf(f3.y - m);
        }
    }
#pragma unroll
    for (int o = 16; o; o >>= 1) {
        float mo = __shfl_xor_sync(0xffffffffu, m, o);
        float so = __shfl_xor_sync(0xffffffffu, sum, o);
        float M = fmaxf(m, mo);
        sum = sum * __expf(m - M) + so * __expf(mo - M);
        m = M;
    }
    __shared__ float sm_m[8], sm_s[8], s_lz;
    if ((tid & 31) == 0) { sm_m[tid >> 5] = m; sm_s[tid >> 5] = sum; }
    __syncthreads();
    if (tid == 0) {
        float M = sm_m[0], S = sm_s[0];
#pragma unroll
        for (int w = 1; w < 8; w++) {
            float mo = sm_m[w], so = sm_s[w];
            float MM = fmaxf(M, mo);
            S = S * __expf(M - MM) + so * __expf(mo - MM);
            M = MM;
        }
        s_lz = M + logf(S);
    }
    __syncthreads();
    const float lz = s_lz;
    float4* dst = (float4*)(out + ((size_t)b * TT + s + 1) * VV);
#pragma unroll
    for (int i = 0; i < 5; i++) {
        int c = tid + i * 256;
        if (c < V8) {
            uint4 u = vals[i];
            float2 f0 = __half22float2(*(__half2*)&u.x);
            float2 f1 = __half22float2(*(__half2*)&u.y);
            float2 f2 = __half22float2(*(__half2*)&u.z);
            float2 f3 = __half22float2(*(__half2*)&u.w);
            __stcs(&dst[2 * c],
                   make_float4(f0.x - lz, f0.y - lz, f1.x - lz, f1.y - lz));
            __stcs(&dst[2 * c + 1],
                   make_float4(f2.x - lz, f2.y - lz, f3.x - lz, f3.y - lz));
        }
    }
}

// -------------------- launch ------------------------------------------------
extern "C" void kernel_launch(void* const* d_in, const int* in_sizes, int n_in,
                              void* d_out, int out_size) {
    const float* X    = (const float*)d_in[0];
    const float* emb  = (const float*)d_in[1];
    const float* fc1w = (const float*)d_in[2];
    const float* fc1b = (const float*)d_in[3];
    const float* wih  = (const float*)d_in[4];
    const float* whh  = (const float*)d_in[5];
    const float* bih  = (const float*)d_in[6];
    const float* bhh  = (const float*)d_in[7];
    const float* fc2w = (const float*)d_in[8];
    const float* fc2b = (const float*)d_in[9];
    const int*   lab  = (const int*)d_in[10];
    float* out = (float*)d_out;

    __half *pAcat, *pHall, *pW2h, *pWihh, *pLogits;
    float *pBias2, *pGpre;
    cudaGetSymbolAddress((void**)&pAcat,   d_Acat);
    cudaGetSymbolAddress((void**)&pBias2,  d_bias2);
    cudaGetSymbolAddress((void**)&pGpre,   d_gpre);
    cudaGetSymbolAddress((void**)&pHall,   d_Hall);
    cudaGetSymbolAddress((void**)&pLogits, d_logits);
    cudaGetSymbolAddress((void**)&pW2h,    d_w2h);
    cudaGetSymbolAddress((void**)&pWihh,   d_wihh);

    k_fc1<<<dim3(8, 16), 256>>>(X, fc1w);
    k_fc1red<<<18, 256>>>(fc1b, lab, bih, bhh);
    k_cvtall<<<RALL / 256, 256>>>(emb, wih, fc2w);

    // gpre: [1984,1024] = Acat[1984,576] @ wihh[1024,576]^T + (bih+bhh)
    k_hgemm<float><<<dim3(8, 16), 256>>>(pAcat, KAP, pWihh, KAP, pBias2,
                                         pGpre, GG, MROWS, GG, KAP);

    // recurrence: 32 CTAs = 4 clusters x 8 (cluster barrier between steps)
    k_rec<<<32, 256>>>(whh);

    // fc2: logits[1984,10000] (fp16) = Hall @ w2h^T + fc2b
    k_hgemm<__half><<<dim3(79, 16), 256>>>(pHall, HH, pW2h, HH, fc2b,
                                           pLogits, VV, MROWS, VV, HH);

    k_softmax<<<MROWS + BB, 256>>>(out);
}

// round 11
// speedup vs baseline: 1.5638x; 1.0104x over previous
#include <cuda_runtime.h>
#include <cuda_fp16.h>
#include <math.h>
#include <stdint.h>

// Problem dims
constexpr int BB = 64;
constexpr int TT = 32;
constexpr int SS = 31;     // scan steps (T-1)
constexpr int VV = 10000;
constexpr int EE = 300;
constexpr int HH = 256;
constexpr int FF = 4096;
constexpr int GG = 1024;   // 4*H
constexpr int KIN = HH + EE;   // 556
constexpr int KAP = 576;       // KIN padded to 32-multiple
constexpr int MROWS = SS * BB; // 1984

// -------------------- device scratch (static, no allocs) --------------------
__device__ float  d_Xp[BB * HH];
__device__ float  d_xpart[16 * BB * HH];
__device__ __half d_Acat[MROWS * KAP];     // [Xp | emb | 0] fp16
__device__ float  d_bias2[GG];             // b_ih + b_hh
__device__ float  d_gpre[MROWS * GG];      // precomputed gate inputs (fp32)
__device__ __half d_Hall[MROWS * HH];      // h history fp16 (fc2 A matrix)
__device__ __half d_logits[MROWS * VV];    // fc2 output, fp16 (40 MB)
__device__ int    d_labels[TT * BB];
__device__ __half d_w2h[VV * HH];          // fc2_w fp16
__device__ __half d_wihh[GG * KAP];        // w_ih fp16, K-padded

// -------------------- helpers ------------------------------------------------
__device__ __forceinline__ uint32_t smem_u32(const void* p) {
    return (uint32_t)__cvta_generic_to_shared(p);
}
__device__ __forceinline__ void cp16(void* smem_dst, const void* gsrc, bool pred) {
    uint32_t saddr = smem_u32(smem_dst);
    int sz = pred ? 16 : 0;
    asm volatile("cp.async.cg.shared.global [%0], [%1], 16, %2;\n"
                 :: "r"(saddr), "l"(gsrc), "r"(sz) : "memory");
}
__device__ __forceinline__ void mma_f16(float* d, const uint32_t* a, const uint32_t* b) {
    asm volatile(
        "mma.sync.aligned.m16n8k16.row.col.f32.f16.f16.f32 "
        "{%0,%1,%2,%3}, {%4,%5,%6,%7}, {%8,%9}, {%0,%1,%2,%3};"
        : "+f"(d[0]), "+f"(d[1]), "+f"(d[2]), "+f"(d[3])
        : "r"(a[0]), "r"(a[1]), "r"(a[2]), "r"(a[3]), "r"(b[0]), "r"(b[1]));
}
// ldmatrix x4 (non-transposed): lanes 0-15 supply row addrs at k+0,
// lanes 16-31 at k+8; returns a0..a3-ordered fragments for m16n8k16.
__device__ __forceinline__ void ldsm_x4(uint32_t& r0, uint32_t& r1,
                                        uint32_t& r2, uint32_t& r3, uint32_t addr) {
    asm volatile("ldmatrix.sync.aligned.m8n8.x4.shared.b16 {%0,%1,%2,%3}, [%4];"
                 : "=r"(r0), "=r"(r1), "=r"(r2), "=r"(r3) : "r"(addr));
}
__device__ __forceinline__ uint2 pack_h4(float4 v) {
    __half2 p0 = __floats2half2_rn(v.x, v.y);
    __half2 p1 = __floats2half2_rn(v.z, v.w);
    uint2 u;
    u.x = *(uint32_t*)&p0;
    u.y = *(uint32_t*)&p1;
    return u;
}
__device__ __forceinline__ float fast_tanh(float x) {
    float r;
    asm("tanh.approx.f32 %0, %1;" : "=f"(r) : "f"(x));
    return r;
}
__device__ __forceinline__ float fast_sigmoid(float x) {
    return 1.f / (1.f + __expf(-x));
}

// -------------------- fc1: Xp = X @ fc1_w.T + b (split-K SIMT) ---------------
__global__ void __launch_bounds__(256) k_fc1(const float* __restrict__ X,
                                             const float* __restrict__ W) {
    const int h0 = blockIdx.x * 32;
    const int kb = blockIdx.y;
    const int kbase = kb * 256;
    const int tid = threadIdx.x;
    __shared__ __align__(16) float Xs[32][68];
    __shared__ float Wsh[32][33];
    float acc[4][2];
#pragma unroll
    for (int q = 0; q < 4; q++) { acc[q][0] = 0.f; acc[q][1] = 0.f; }
    const int tb = (tid & 15) * 4;
    const int th = (tid >> 4) * 2;

    for (int t = 0; t < 8; t++) {
        int k0 = kbase + t * 32;
#pragma unroll
        for (int i = 0; i < 8; i++) {
            int idx = tid + i * 256;
            int b = idx >> 5, kk = idx & 31;
            Xs[kk][b] = X[(size_t)b * FF + k0 + kk];
        }
#pragma unroll
        for (int i = 0; i < 4; i++) {
            int idx = tid + i * 256;
            int hh = idx >> 5, kk = idx & 31;
            Wsh[kk][hh] = W[(size_t)(h0 + hh) * FF + k0 + kk];
        }
        __syncthreads();
#pragma unroll
        for (int kk = 0; kk < 32; kk++) {
            float4 x4 = *(const float4*)&Xs[kk][tb];
            float w0 = Wsh[kk][th], w1 = Wsh[kk][th + 1];
            acc[0][0] += x4.x * w0; acc[0][1] += x4.x * w1;
            acc[1][0] += x4.y * w0; acc[1][1] += x4.y * w1;
            acc[2][0] += x4.z * w0; acc[2][1] += x4.z * w1;
            acc[3][0] += x4.w * w0; acc[3][1] += x4.w * w1;
        }
        __syncthreads();
    }
#pragma unroll
    for (int q = 0; q < 4; q++)
#pragma unroll
        for (int j = 0; j < 2; j++)
            d_xpart[kb * (BB * HH) + (tb + q) * HH + h0 + th + j] = acc[q][j];
}

// -------------------- fc1 reduce + fused prep (blocks 16/17) -----------------
__global__ void k_fc1red(const float* __restrict__ fc1_b,
                         const int* __restrict__ lab,
                         const float* __restrict__ bih,
                         const float* __restrict__ bhh) {
    const int blk = blockIdx.x;
    const int tid = threadIdx.x;
    if (blk < 16) {
        int i4 = blk * 256 + tid;
        const float4* bp = (const float4*)fc1_b;
        float4 s = bp[i4 & 63];
#pragma unroll
        for (int kb = 0; kb < 16; kb++) {
            float4 p = ((const float4*)(d_xpart + kb * BB * HH))[i4];
            s.x += p.x; s.y += p.y; s.z += p.z; s.w += p.w;
        }
        ((float4*)d_Xp)[i4] = s;
    } else if (blk == 16) {
        __shared__ int is64;
        if (tid == 0) {
            int f = 1;
            for (int i = 1; i < 64 && f; i += 2)
                if (lab[i] != 0) f = 0;
            is64 = f;
        }
        __syncthreads();
        for (int i = tid; i < TT * BB; i += 256)
            d_labels[i] = is64 ? (int)(((const long long*)lab)[i]) : lab[i];
    } else {
        for (int i = tid; i < GG; i += 256)
            d_bias2[i] = bih[i] + bhh[i];
    }
}

// -------------------- merged elementwise: buildA + wih cvt + fc2w cvt --------
constexpr int AC4 = KAP / 4;               // 144 groups per row
constexpr int R1 = MROWS * AC4;            // 285696
constexpr int R2 = GG * AC4;               // 147456
constexpr int R3 = VV * HH / 4;            // 640000
constexpr int RALL = R1 + R2 + R3;         // 1073152
__global__ void __launch_bounds__(256) k_cvtall(const float* __restrict__ emb_table,
                                                const float* __restrict__ wih,
                                                const float* __restrict__ fc2w) {
    int idx = blockIdx.x * 256 + threadIdx.x;
    if (idx < R1) {                        // Acat = [Xp | emb | 0]
        int r = idx / AC4, c = idx - r * AC4;
        int s = r >> 6, b = r & 63;
        float4 v;
        if (c < 64) {
            v = ((const float4*)d_Xp)[b * 64 + c];
        } else if (c < 139) {
            int tok = (s == 0) ? 1 : d_labels[s * BB + b];   // START_ID = 1
            v = *(const float4*)(emb_table + (size_t)tok * EE + (c - 64) * 4);
        } else {
            v = make_float4(0.f, 0.f, 0.f, 0.f);
        }
        ((uint2*)d_Acat)[idx] = pack_h4(v);
    } else if (idx < R1 + R2) {            // w_ih -> fp16, K-padded
        int i = idx - R1;
        int r = i / AC4, c = i - r * AC4;
        float4 v = (c < 139) ? *(const float4*)(wih + (size_t)r * KIN + c * 4)
                             : make_float4(0.f, 0.f, 0.f, 0.f);
        ((uint2*)d_wihh)[i] = pack_h4(v);
    } else if (idx < RALL) {               // fc2_w -> fp16
        int i = idx - (R1 + R2);
        ((uint2*)d_w2h)[i] = pack_h4(((const float4*)fc2w)[i]);
    }
}

// -------------------- fp16 tensor-core GEMM (ldmatrix operand loads) ---------
// C[M,N] = A[M,K] @ B[N,K]^T + bias[N]; 128x128 tile, BK=32, 8 warps,
// m16n8k16 f16/f32-acc.  Fragments via ldmatrix.x4: 12 LDSM per k-tile per
// warp instead of 96 scalar LDS.
template <typename OT>
__global__ void __launch_bounds__(256) k_hgemm(
    const __half* __restrict__ A, int lda,
    const __half* __restrict__ B, int ldb,
    const float* __restrict__ bias,
    OT* __restrict__ C, int ldc,
    int M, int N, int K)
{
    __shared__ __align__(16) __half As[2][128][40];
    __shared__ __align__(16) __half Bs[2][128][40];

    const int tid = threadIdx.x;
    const int lane = tid & 31;
    const int warpId = tid >> 5;
    const int warpM = warpId & 3;
    const int warpN = warpId >> 2;
    const int g = lane >> 2;
    const int t = lane & 3;
    const int lr16 = lane & 15;          // ldmatrix row within 16-row group
    const int lk8 = (lane >> 4) * 8;     // ldmatrix k offset (0 or 8)

    const int ncol = blockIdx.x * 128;
    const int mrow = blockIdx.y * 128;

    float acc[2][8][4];
#pragma unroll
    for (int mt = 0; mt < 2; mt++)
#pragma unroll
        for (int nt = 0; nt < 8; nt++)
#pragma unroll
            for (int q = 0; q < 4; q++) acc[mt][nt][q] = 0.f;

    const int NT = K >> 5;

    auto load_tile = [&](int buf, int kt) {
        int k0 = kt << 5;
#pragma unroll
        for (int i = 0; i < 2; i++) {
            int c = tid + i * 256;
            int m = c >> 2, kc = (c & 3) * 8;
            cp16(&As[buf][m][kc], A + (size_t)(mrow + m) * lda + k0 + kc,
                 (mrow + m) < M);
        }
#pragma unroll
        for (int i = 0; i < 2; i++) {
            int c = tid + i * 256;
            int n = c >> 2, kc = (c & 3) * 8;
            cp16(&Bs[buf][n][kc], B + (size_t)(ncol + n) * ldb + k0 + kc,
                 (ncol + n) < N);
        }
    };

    load_tile(0, 0);
    asm volatile("cp.async.commit_group;\n" ::: "memory");

    for (int kt = 0; kt < NT; kt++) {
        int buf = kt & 1;
        if (kt + 1 < NT) {
            load_tile(buf ^ 1, kt + 1);
            asm volatile("cp.async.commit_group;\n" ::: "memory");
            asm volatile("cp.async.wait_group 1;\n" ::: "memory");
        } else {
            asm volatile("cp.async.wait_group 0;\n" ::: "memory");
        }
        __syncthreads();

#pragma unroll
        for (int ks = 0; ks < 32; ks += 16) {
            uint32_t afr[2][4], bfr[8][2];
#pragma unroll
            for (int mt = 0; mt < 2; mt++) {
                ldsm_x4(afr[mt][0], afr[mt][1], afr[mt][2], afr[mt][3],
                        smem_u32(&As[buf][warpM * 32 + mt * 16 + lr16][ks + lk8]));
            }
#pragma unroll
            for (int ntp = 0; ntp < 4; ntp++) {
                uint32_t q0, q1, q2, q3;
                ldsm_x4(q0, q1, q2, q3,
                        smem_u32(&Bs[buf][warpN * 64 + ntp * 16 + lr16][ks + lk8]));
                bfr[2 * ntp][0]     = q0;
                bfr[2 * ntp + 1][0] = q1;
                bfr[2 * ntp][1]     = q2;
                bfr[2 * ntp + 1][1] = q3;
            }
#pragma unroll
            for (int mt = 0; mt < 2; mt++)
#pragma unroll
                for (int nt = 0; nt < 8; nt++)
                    mma_f16(acc[mt][nt], afr[mt], bfr[nt]);
        }
        __syncthreads();
    }

#pragma unroll
    for (int mt = 0; mt < 2; mt++) {
#pragma unroll
        for (int nt = 0; nt < 8; nt++) {
            int m0 = mrow + warpM * 32 + mt * 16 + g;
            int n0 = ncol + warpN * 64 + nt * 8 + 2 * t;
            if (n0 < N) {
                float b0 = bias[n0], b1 = bias[n0 + 1];
                float v0 = acc[mt][nt][0] + b0, v1 = acc[mt][nt][1] + b1;
                float v2 = acc[mt][nt][2] + b0, v3 = acc[mt][nt][3] + b1;
                if (sizeof(OT) == 4) {       // fp32 store
                    float* Cp = (float*)C;
                    if (m0 < M) {
                        Cp[(size_t)m0 * ldc + n0]     = v0;
                        Cp[(size_t)m0 * ldc + n0 + 1] = v1;
                    }
                    if (m0 + 8 < M) {
                        Cp[(size_t)(m0 + 8) * ldc + n0]     = v2;
                        Cp[(size_t)(m0 + 8) * ldc + n0 + 1] = v3;
                    }
                } else {                     // fp16 half2 store
                    __half* Cp = (__half*)C;
                    if (m0 < M) {
                        __half2 h01 = __floats2half2_rn(v0, v1);
                        *(uint32_t*)&Cp[(size_t)m0 * ldc + n0] = *(uint32_t*)&h01;
                    }
                    if (m0 + 8 < M) {
                        __half2 h23 = __floats2half2_rn(v2, v3);
                        *(uint32_t*)&Cp[(size_t)(m0 + 8) * ldc + n0] = *(uint32_t*)&h23;
                    }
                }
            }
        }
    }
}

// -------------------- recurrence: 4 clusters x 8 CTAs ------------------------
// Cluster barrier between steps; w_hh fragments register-resident; h fragments
// via one ldmatrix.x4 per k-step (was 4 scalar LDS).
__global__ void __launch_bounds__(256, 1) __cluster_dims__(8, 1, 1)
k_rec(const float* __restrict__ w_hh) {
    __shared__ __align__(16) __half hs[16][264];   // h_prev (16 rows x 256)
    __shared__ float gbuf[16][132];                // gate exchange (128 cols)

    const int tid = threadIdx.x;
    const int lane = tid & 31;
    const int wid = tid >> 5;
    const int g = lane >> 2;
    const int t = lane & 3;
    const int lr16 = lane & 15;
    const int lk8 = (lane >> 4) * 8;
    const int rank = blockIdx.x & 7;
    const int grp = blockIdx.x >> 3;
    const int j0 = rank * 32;
    const int brow0 = grp * 16;

    uint32_t wb[2][16][2];
#pragma unroll
    for (int nt = 0; nt < 2; nt++) {
        int lc = wid * 16 + nt * 8 + g;
        int wrow = (lc >> 5) * 256 + j0 + (lc & 31);
        const float* wr = w_hh + (size_t)wrow * HH;
#pragma unroll
        for (int kt = 0; kt < 16; kt++) {
            __half2 h0 = __floats2half2_rn(wr[kt * 16 + 2 * t], wr[kt * 16 + 2 * t + 1]);
            __half2 h1 = __floats2half2_rn(wr[kt * 16 + 2 * t + 8], wr[kt * 16 + 2 * t + 9]);
            wb[nt][kt][0] = *(uint32_t*)&h0;
            wb[nt][kt][1] = *(uint32_t*)&h1;
        }
    }

    float creg[2] = {0.f, 0.f};
    const int crow = tid >> 4;
    const int cj2 = (tid & 15) * 2;
    int lc0[2], r0[2];
#pragma unroll
    for (int nt = 0; nt < 2; nt++) {
        lc0[nt] = wid * 16 + nt * 8 + 2 * t;
        r0[nt] = (lc0[nt] >> 5) * 256 + j0 + (lc0[nt] & 31);
    }

    for (int s = 0; s < SS; s++) {
        const float* gp = d_gpre + ((size_t)s * BB + brow0) * GG;
        float2 q0[2], q1[2];
#pragma unroll
        for (int nt = 0; nt < 2; nt++) {
            q0[nt] = *(const float2*)&gp[(size_t)g * GG + r0[nt]];
            q1[nt] = *(const float2*)&gp[(size_t)(g + 8) * GG + r0[nt]];
        }

        float accA[2][4] = {{0.f, 0.f, 0.f, 0.f}, {0.f, 0.f, 0.f, 0.f}};
        float accB[2][4] = {{0.f, 0.f, 0.f, 0.f}, {0.f, 0.f, 0.f, 0.f}};

        if (s > 0) {
            const uint4* src = (const uint4*)(d_Hall + ((size_t)(s - 1) * BB + brow0) * HH);
#pragma unroll
            for (int i = 0; i < 2; i++) {
                int c = tid + i * 256;
                int m = c >> 5, kc = c & 31;
                *(uint4*)&hs[m][kc * 8] = src[m * 32 + kc];
            }
            __syncthreads();
#pragma unroll
            for (int kt = 0; kt < 16; kt++) {
                uint32_t af[4];
                ldsm_x4(af[0], af[1], af[2], af[3],
                        smem_u32(&hs[lr16][kt * 16 + lk8]));
                float* d0 = (kt < 8) ? accA[0] : accB[0];
                float* d1 = (kt < 8) ? accA[1] : accB[1];
                mma_f16(d0, af, wb[0][kt]);
                mma_f16(d1, af, wb[1][kt]);
            }
        }

#pragma unroll
        for (int nt = 0; nt < 2; nt++) {
            gbuf[g][lc0[nt]]         = accA[nt][0] + accB[nt][0] + q0[nt].x;
            gbuf[g][lc0[nt] + 1]     = accA[nt][1] + accB[nt][1] + q0[nt].y;
            gbuf[g + 8][lc0[nt]]     = accA[nt][2] + accB[nt][2] + q1[nt].x;
            gbuf[g + 8][lc0[nt] + 1] = accA[nt][3] + accB[nt][3] + q1[nt].y;
        }
        __syncthreads();

        {
            float hv[2];
#pragma unroll
            for (int e = 0; e < 2; e++) {
                int jj = cj2 + e;
                float gi = gbuf[crow][jj],      gf = gbuf[crow][32 + jj];
                float gc = gbuf[crow][64 + jj], go = gbuf[crow][96 + jj];
                float ii = fast_sigmoid(gi);
                float ff = fast_sigmoid(gf);
                float gv = fast_tanh(gc);
                float oo = fast_sigmoid(go);
                float cn = ff * creg[e] + ii * gv;
                creg[e] = cn;
                hv[e] = oo * fast_tanh(cn);
            }
            __half2 hp = __floats2half2_rn(hv[0], hv[1]);
            *(uint32_t*)&d_Hall[((size_t)s * BB + brow0 + crow) * HH + j0 + cj2] =
                *(uint32_t*)&hp;
        }

        if (s + 1 < SS) {
            asm volatile("barrier.cluster.arrive.aligned;" ::: "memory");
            asm volatile("barrier.cluster.wait.aligned;" ::: "memory");
        }
    }
}

// -------------------- fused one-hot + log-softmax (register-cached row) ------
constexpr int V8 = VV / 8;   // 1250 uint4 groups
__global__ void __launch_bounds__(256) k_softmax(float* __restrict__ out) {
    const int r = blockIdx.x;
    const int tid = threadIdx.x;
    if (r >= MROWS) {                      // one-hot t=0 plane
        int b = r - MROWS;
        float* dst = out + (size_t)b * TT * VV;
        for (int v = tid * 4; v < VV; v += 1024) {
            float4 z = make_float4(0.f, 0.f, 0.f, 0.f);
            if (v == 0) z.y = 1.f;         // index 1 = START_ID
            __stcs((float4*)(dst + v), z);
        }
        return;
    }
    const int s = r >> 6, b = r & 63;
    const uint4* src = (const uint4*)(d_logits + (size_t)r * VV);

    uint4 vals[5];
    float m = -1e30f, sum = 0.f;
#pragma unroll
    for (int i = 0; i < 5; i++) {
        int c = tid + i * 256;
        if (c < V8) {
            uint4 u = src[c];
            vals[i] = u;
            float2 f0 = __half22float2(*(__half2*)&u.x);
            float2 f1 = __half22float2(*(__half2*)&u.y);
            float2 f2 = __half22float2(*(__half2*)&u.z);
            float2 f3 = __half22float2(*(__half2*)&u.w);
            float m8 = fmaxf(fmaxf(fmaxf(f0.x, f0.y), fmaxf(f1.x, f1.y)),
                             fmaxf(fmaxf(f2.x, f2.y), fmaxf(f3.x, f3.y)));
            if (m8 > m) { sum *= __expf(m - m8); m = m8; }
            sum += __expf(f0.x - m) + __expf(f0.y - m)
                 + __expf(f1.x - m) + __expf(f1.y - m)
                 + __expf(f2.x - m) + __expf(f2.y - m)
                 + __expf(f3.x - m) + __expf(f3.y - m);
        }
    }
#pragma unroll
    for (int o = 16; o; o >>= 1) {
        float mo = __shfl_xor_sync(0xffffffffu, m, o);
        float so = __shfl_xor_sync(0xffffffffu, sum, o);
        float M = fmaxf(m, mo);
        sum = sum * __expf(m - M) + so * __expf(mo - M);
        m = M;
    }
    __shared__ float sm_m[8], sm_s[8], s_lz;
    if ((tid & 31) == 0) { sm_m[tid >> 5] = m; sm_s[tid >> 5] = sum; }
    __syncthreads();
    if (tid == 0) {
        float M = sm_m[0], S = sm_s[0];
#pragma unroll
        for (int w = 1; w < 8; w++) {
            float mo = sm_m[w], so = sm_s[w];
            float MM = fmaxf(M, mo);
            S = S * __expf(M - MM) + so * __expf(mo - MM);
            M = MM;
        }
        s_lz = M + logf(S);
    }
    __syncthreads();
    const float lz = s_lz;
    float4* dst = (float4*)(out + ((size_t)b * TT + s + 1) * VV);
#pragma unroll
    for (int i = 0; i < 5; i++) {
        int c = tid + i * 256;
        if (c < V8) {
            uint4 u = vals[i];
            float2 f0 = __half22float2(*(__half2*)&u.x);
            float2 f1 = __half22float2(*(__half2*)&u.y);
            float2 f2 = __half22float2(*(__half2*)&u.z);
            float2 f3 = __half22float2(*(__half2*)&u.w);
            __stcs(&dst[2 * c],
                   make_float4(f0.x - lz, f0.y - lz, f1.x - lz, f1.y - lz));
            __stcs(&dst[2 * c + 1],
                   make_float4(f2.x - lz, f2.y - lz, f3.x - lz, f3.y - lz));
        }
    }
}

// -------------------- launch ------------------------------------------------
extern "C" void kernel_launch(void* const* d_in, const int* in_sizes, int n_in,
                              void* d_out, int out_size) {
    const float* X    = (const float*)d_in[0];
    const float* emb  = (const float*)d_in[1];
    const float* fc1w = (const float*)d_in[2];
    const float* fc1b = (const float*)d_in[3];
    const float* wih  = (const float*)d_in[4];
    const float* whh  = (const float*)d_in[5];
    const float* bih  = (const float*)d_in[6];
    const float* bhh  = (const float*)d_in[7];
    const float* fc2w = (const float*)d_in[8];
    const float* fc2b = (const float*)d_in[9];
    const int*   lab  = (const int*)d_in[10];
    float* out = (float*)d_out;

    __half *pAcat, *pHall, *pW2h, *pWihh, *pLogits;
    float *pBias2, *pGpre;
    cudaGetSymbolAddress((void**)&pAcat,   d_Acat);
    cudaGetSymbolAddress((void**)&pBias2,  d_bias2);
    cudaGetSymbolAddress((void**)&pGpre,   d_gpre);
    cudaGetSymbolAddress((void**)&pHall,   d_Hall);
    cudaGetSymbolAddress((void**)&pLogits, d_logits);
    cudaGetSymbolAddress((void**)&pW2h,    d_w2h);
    cudaGetSymbolAddress((void**)&pWihh,   d_wihh);

    k_fc1<<<dim3(8, 16), 256>>>(X, fc1w);
    k_fc1red<<<18, 256>>>(fc1b, lab, bih, bhh);
    k_cvtall<<<RALL / 256, 256>>>(emb, wih, fc2w);

    // gpre: [1984,1024] = Acat[1984,576] @ wihh[1024,576]^T + (bih+bhh)
    k_hgemm<float><<<dim3(8, 16), 256>>>(pAcat, KAP, pWihh, KAP, pBias2,
                                         pGpre, GG, MROWS, GG, KAP);

    // recurrence: 32 CTAs = 4 clusters x 8 (cluster barrier between steps)
    k_rec<<<32, 256>>>(whh);

    // fc2: logits[1984,10000] (fp16) = Hall @ w2h^T + fc2b
    k_hgemm<__half><<<dim3(79, 16), 256>>>(pHall, HH, pW2h, HH, fc2b,
                                           pLogits, VV, MROWS, VV, HH);

    k_softmax<<<MROWS + BB, 256>>>(out);
}

// round 12
// speedup vs baseline: 1.5757x; 1.0076x over previous
#include <cuda_runtime.h>
#include <cuda_fp16.h>
#include <math.h>
#include <stdint.h>

// Problem dims
constexpr int BB = 64;
constexpr int TT = 32;
constexpr int SS = 31;     // scan steps (T-1)
constexpr int VV = 10000;
constexpr int EE = 300;
constexpr int HH = 256;
constexpr int FF = 4096;
constexpr int GG = 1024;   // 4*H
constexpr int KIN = HH + EE;   // 556
constexpr int KAP = 576;       // KIN padded to 32-multiple
constexpr int MROWS = SS * BB; // 1984

// -------------------- device scratch (static, no allocs) --------------------
__device__ float  d_Xp[BB * HH];
__device__ float  d_xpart[16 * BB * HH];
__device__ __half d_Acat[MROWS * KAP];     // [Xp | emb | 0] fp16
__device__ float  d_bias2[GG];             // b_ih + b_hh
__device__ float  d_gpre[MROWS * GG];      // precomputed gate inputs (fp32)
__device__ __half d_Hall[MROWS * HH];      // h history fp16 (fc2 A matrix)
__device__ __half d_logits[MROWS * VV];    // fc2 output, fp16 (40 MB)
__device__ int    d_labels[TT * BB];
__device__ __half d_w2h[VV * HH];          // fc2_w fp16
__device__ __half d_wihh[GG * KAP];        // w_ih fp16, K-padded

// -------------------- helpers ------------------------------------------------
__device__ __forceinline__ uint32_t smem_u32(const void* p) {
    return (uint32_t)__cvta_generic_to_shared(p);
}
__device__ __forceinline__ void cp16(void* smem_dst, const void* gsrc, bool pred) {
    uint32_t saddr = smem_u32(smem_dst);
    int sz = pred ? 16 : 0;
    asm volatile("cp.async.cg.shared.global [%0], [%1], 16, %2;\n"
                 :: "r"(saddr), "l"(gsrc), "r"(sz) : "memory");
}
__device__ __forceinline__ void mma_f16(float* d, const uint32_t* a, const uint32_t* b) {
    asm volatile(
        "mma.sync.aligned.m16n8k16.row.col.f32.f16.f16.f32 "
        "{%0,%1,%2,%3}, {%4,%5,%6,%7}, {%8,%9}, {%0,%1,%2,%3};"
        : "+f"(d[0]), "+f"(d[1]), "+f"(d[2]), "+f"(d[3])
        : "r"(a[0]), "r"(a[1]), "r"(a[2]), "r"(a[3]), "r"(b[0]), "r"(b[1]));
}
__device__ __forceinline__ void ldsm_x4(uint32_t& r0, uint32_t& r1,
                                        uint32_t& r2, uint32_t& r3, uint32_t addr) {
    asm volatile("ldmatrix.sync.aligned.m8n8.x4.shared.b16 {%0,%1,%2,%3}, [%4];"
                 : "=r"(r0), "=r"(r1), "=r"(r2), "=r"(r3) : "r"(addr));
}
__device__ __forceinline__ uint2 pack_h4(float4 v) {
    __half2 p0 = __floats2half2_rn(v.x, v.y);
    __half2 p1 = __floats2half2_rn(v.z, v.w);
    uint2 u;
    u.x = *(uint32_t*)&p0;
    u.y = *(uint32_t*)&p1;
    return u;
}
__device__ __forceinline__ float fast_tanh(float x) {
    float r;
    asm("tanh.approx.f32 %0, %1;" : "=f"(r) : "f"(x));
    return r;
}
__device__ __forceinline__ float fast_sigmoid(float x) {
    return 1.f / (1.f + __expf(-x));
}

// -------------------- fc1: Xp = X @ fc1_w.T + b (split-K SIMT) ---------------
__global__ void __launch_bounds__(256) k_fc1(const float* __restrict__ X,
                                             const float* __restrict__ W) {
    const int h0 = blockIdx.x * 32;
    const int kb = blockIdx.y;
    const int kbase = kb * 256;
    const int tid = threadIdx.x;
    __shared__ __align__(16) float Xs[32][68];
    __shared__ float Wsh[32][33];
    float acc[4][2];
#pragma unroll
    for (int q = 0; q < 4; q++) { acc[q][0] = 0.f; acc[q][1] = 0.f; }
    const int tb = (tid & 15) * 4;
    const int th = (tid >> 4) * 2;

    for (int t = 0; t < 8; t++) {
        int k0 = kbase + t * 32;
#pragma unroll
        for (int i = 0; i < 8; i++) {
            int idx = tid + i * 256;
            int b = idx >> 5, kk = idx & 31;
            Xs[kk][b] = X[(size_t)b * FF + k0 + kk];
        }
#pragma unroll
        for (int i = 0; i < 4; i++) {
            int idx = tid + i * 256;
            int hh = idx >> 5, kk = idx & 31;
            Wsh[kk][hh] = W[(size_t)(h0 + hh) * FF + k0 + kk];
        }
        __syncthreads();
#pragma unroll
        for (int kk = 0; kk < 32; kk++) {
            float4 x4 = *(const float4*)&Xs[kk][tb];
            float w0 = Wsh[kk][th], w1 = Wsh[kk][th + 1];
            acc[0][0] += x4.x * w0; acc[0][1] += x4.x * w1;
            acc[1][0] += x4.y * w0; acc[1][1] += x4.y * w1;
            acc[2][0] += x4.z * w0; acc[2][1] += x4.z * w1;
            acc[3][0] += x4.w * w0; acc[3][1] += x4.w * w1;
        }
        __syncthreads();
    }
#pragma unroll
    for (int q = 0; q < 4; q++)
#pragma unroll
        for (int j = 0; j < 2; j++)
            d_xpart[kb * (BB * HH) + (tb + q) * HH + h0 + th + j] = acc[q][j];
}

// -------------------- fc1 reduce + fused prep (blocks 16/17) -----------------
__global__ void k_fc1red(const float* __restrict__ fc1_b,
                         const int* __restrict__ lab,
                         const float* __restrict__ bih,
                         const float* __restrict__ bhh) {
    const int blk = blockIdx.x;
    const int tid = threadIdx.x;
    if (blk < 16) {
        int i4 = blk * 256 + tid;
        const float4* bp = (const float4*)fc1_b;
        float4 s = bp[i4 & 63];
#pragma unroll
        for (int kb = 0; kb < 16; kb++) {
            float4 p = ((const float4*)(d_xpart + kb * BB * HH))[i4];
            s.x += p.x; s.y += p.y; s.z += p.z; s.w += p.w;
        }
        ((float4*)d_Xp)[i4] = s;
    } else if (blk == 16) {
        __shared__ int is64;
        if (tid == 0) {
            int f = 1;
            for (int i = 1; i < 64 && f; i += 2)
                if (lab[i] != 0) f = 0;
            is64 = f;
        }
        __syncthreads();
        for (int i = tid; i < TT * BB; i += 256)
            d_labels[i] = is64 ? (int)(((const long long*)lab)[i]) : lab[i];
    } else {
        for (int i = tid; i < GG; i += 256)
            d_bias2[i] = bih[i] + bhh[i];
    }
}

// -------------------- merged elementwise: buildA + wih cvt + fc2w cvt --------
constexpr int AC4 = KAP / 4;               // 144 groups per row
constexpr int R1 = MROWS * AC4;            // 285696
constexpr int R2 = GG * AC4;               // 147456
constexpr int R3 = VV * HH / 4;            // 640000
constexpr int RALL = R1 + R2 + R3;         // 1073152
__global__ void __launch_bounds__(256) k_cvtall(const float* __restrict__ emb_table,
                                                const float* __restrict__ wih,
                                                const float* __restrict__ fc2w) {
    int idx = blockIdx.x * 256 + threadIdx.x;
    if (idx < R1) {                        // Acat = [Xp | emb | 0]
        int r = idx / AC4, c = idx - r * AC4;
        int s = r >> 6, b = r & 63;
        float4 v;
        if (c < 64) {
            v = ((const float4*)d_Xp)[b * 64 + c];
        } else if (c < 139) {
            int tok = (s == 0) ? 1 : d_labels[s * BB + b];   // START_ID = 1
            v = *(const float4*)(emb_table + (size_t)tok * EE + (c - 64) * 4);
        } else {
            v = make_float4(0.f, 0.f, 0.f, 0.f);
        }
        ((uint2*)d_Acat)[idx] = pack_h4(v);
    } else if (idx < R1 + R2) {            // w_ih -> fp16, K-padded
        int i = idx - R1;
        int r = i / AC4, c = i - r * AC4;
        float4 v = (c < 139) ? *(const float4*)(wih + (size_t)r * KIN + c * 4)
                             : make_float4(0.f, 0.f, 0.f, 0.f);
        ((uint2*)d_wihh)[i] = pack_h4(v);
    } else if (idx < RALL) {               // fc2_w -> fp16
        int i = idx - (R1 + R2);
        ((uint2*)d_w2h)[i] = pack_h4(((const float4*)fc2w)[i]);
    }
}

// -------------------- fp16 TC GEMM, 128x128 tile (fc2) -----------------------
template <typename OT>
__global__ void __launch_bounds__(256) k_hgemm(
    const __half* __restrict__ A, int lda,
    const __half* __restrict__ B, int ldb,
    const float* __restrict__ bias,
    OT* __restrict__ C, int ldc,
    int M, int N, int K)
{
    __shared__ __align__(16) __half As[2][128][40];
    __shared__ __align__(16) __half Bs[2][128][40];

    const int tid = threadIdx.x;
    const int lane = tid & 31;
    const int warpId = tid >> 5;
    const int warpM = warpId & 3;
    const int warpN = warpId >> 2;
    const int g = lane >> 2;
    const int t = lane & 3;
    const int lr16 = lane & 15;
    const int lk8 = (lane >> 4) * 8;

    const int ncol = blockIdx.x * 128;
    const int mrow = blockIdx.y * 128;

    float acc[2][8][4];
#pragma unroll
    for (int mt = 0; mt < 2; mt++)
#pragma unroll
        for (int nt = 0; nt < 8; nt++)
#pragma unroll
            for (int q = 0; q < 4; q++) acc[mt][nt][q] = 0.f;

    const int NT = K >> 5;

    auto load_tile = [&](int buf, int kt) {
        int k0 = kt << 5;
#pragma unroll
        for (int i = 0; i < 2; i++) {
            int c = tid + i * 256;
            int m = c >> 2, kc = (c & 3) * 8;
            cp16(&As[buf][m][kc], A + (size_t)(mrow + m) * lda + k0 + kc,
                 (mrow + m) < M);
        }
#pragma unroll
        for (int i = 0; i < 2; i++) {
            int c = tid + i * 256;
            int n = c >> 2, kc = (c & 3) * 8;
            cp16(&Bs[buf][n][kc], B + (size_t)(ncol + n) * ldb + k0 + kc,
                 (ncol + n) < N);
        }
    };

    load_tile(0, 0);
    asm volatile("cp.async.commit_group;\n" ::: "memory");

    for (int kt = 0; kt < NT; kt++) {
        int buf = kt & 1;
        if (kt + 1 < NT) {
            load_tile(buf ^ 1, kt + 1);
            asm volatile("cp.async.commit_group;\n" ::: "memory");
            asm volatile("cp.async.wait_group 1;\n" ::: "memory");
        } else {
            asm volatile("cp.async.wait_group 0;\n" ::: "memory");
        }
        __syncthreads();

#pragma unroll
        for (int ks = 0; ks < 32; ks += 16) {
            uint32_t afr[2][4], bfr[8][2];
#pragma unroll
            for (int mt = 0; mt < 2; mt++) {
                ldsm_x4(afr[mt][0], afr[mt][1], afr[mt][2], afr[mt][3],
                        smem_u32(&As[buf][warpM * 32 + mt * 16 + lr16][ks + lk8]));
            }
#pragma unroll
            for (int ntp = 0; ntp < 4; ntp++) {
                uint32_t q0, q1, q2, q3;
                ldsm_x4(q0, q1, q2, q3,
                        smem_u32(&Bs[buf][warpN * 64 + ntp * 16 + lr16][ks + lk8]));
                bfr[2 * ntp][0]     = q0;
                bfr[2 * ntp + 1][0] = q1;
                bfr[2 * ntp][1]     = q2;
                bfr[2 * ntp + 1][1] = q3;
            }
#pragma unroll
            for (int mt = 0; mt < 2; mt++)
#pragma unroll
                for (int nt = 0; nt < 8; nt++)
                    mma_f16(acc[mt][nt], afr[mt], bfr[nt]);
        }
        __syncthreads();
    }

#pragma unroll
    for (int mt = 0; mt < 2; mt++) {
#pragma unroll
        for (int nt = 0; nt < 8; nt++) {
            int m0 = mrow + warpM * 32 + mt * 16 + g;
            int n0 = ncol + warpN * 64 + nt * 8 + 2 * t;
            if (n0 < N) {
                float b0 = bias[n0], b1 = bias[n0 + 1];
                float v0 = acc[mt][nt][0] + b0, v1 = acc[mt][nt][1] + b1;
                float v2 = acc[mt][nt][2] + b0, v3 = acc[mt][nt][3] + b1;
                if (sizeof(OT) == 4) {
                    float* Cp = (float*)C;
                    if (m0 < M) {
                        Cp[(size_t)m0 * ldc + n0]     = v0;
                        Cp[(size_t)m0 * ldc + n0 + 1] = v1;
                    }
                    if (m0 + 8 < M) {
                        Cp[(size_t)(m0 + 8) * ldc + n0]     = v2;
                        Cp[(size_t)(m0 + 8) * ldc + n0 + 1] = v3;
                    }
                } else {
                    __half* Cp = (__half*)C;
                    if (m0 < M) {
                        __half2 h01 = __floats2half2_rn(v0, v1);
                        *(uint32_t*)&Cp[(size_t)m0 * ldc + n0] = *(uint32_t*)&h01;
                    }
                    if (m0 + 8 < M) {
                        __half2 h23 = __floats2half2_rn(v2, v3);
                        *(uint32_t*)&Cp[(size_t)(m0 + 8) * ldc + n0] = *(uint32_t*)&h23;
                    }
                }
            }
        }
    }
}

// -------------------- fp16 TC GEMM, 64x128 tile (gpre: 248 CTAs) -------------
// Same algorithm, M-tile 64 -> grid (N/128, M/64): more CTAs to hide the
// k-loop latency (the 128x128 version left 1 CTA/SM and 20 SMs idle).
__global__ void __launch_bounds__(256) k_hgemm64(
    const __half* __restrict__ A, int lda,
    const __half* __restrict__ B, int ldb,
    const float* __restrict__ bias,
    float* __restrict__ C, int ldc,
    int M, int N, int K)
{
    __shared__ __align__(16) __half As[2][64][40];
    __shared__ __align__(16) __half Bs[2][128][40];

    const int tid = threadIdx.x;
    const int lane = tid & 31;
    const int warpId = tid >> 5;
    const int warpM = warpId & 1;    // 2 M-warps x 32 rows
    const int warpN = warpId >> 1;   // 4 N-warps x 32 cols
    const int g = lane >> 2;
    const int t = lane & 3;
    const int lr16 = lane & 15;
    const int lk8 = (lane >> 4) * 8;

    const int ncol = blockIdx.x * 128;
    const int mrow = blockIdx.y * 64;

    float acc[2][4][4];
#pragma unroll
    for (int mt = 0; mt < 2; mt++)
#pragma unroll
        for (int nt = 0; nt < 4; nt++)
#pragma unroll
            for (int q = 0; q < 4; q++) acc[mt][nt][q] = 0.f;

    const int NT = K >> 5;

    auto load_tile = [&](int buf, int kt) {
        int k0 = kt << 5;
        {
            int c = tid;                 // 256 chunks cover 64 rows x 32 cols
            int m = c >> 2, kc = (c & 3) * 8;
            cp16(&As[buf][m][kc], A + (size_t)(mrow + m) * lda + k0 + kc,
                 (mrow + m) < M);
        }
#pragma unroll
        for (int i = 0; i < 2; i++) {
            int c = tid + i * 256;
            int n = c >> 2, kc = (c & 3) * 8;
            cp16(&Bs[buf][n][kc], B + (size_t)(ncol + n) * ldb + k0 + kc,
                 (ncol + n) < N);
        }
    };

    load_tile(0, 0);
    asm volatile("cp.async.commit_group;\n" ::: "memory");

    for (int kt = 0; kt < NT; kt++) {
        int buf = kt & 1;
        if (kt + 1 < NT) {
            load_tile(buf ^ 1, kt + 1);
            asm volatile("cp.async.commit_group;\n" ::: "memory");
            asm volatile("cp.async.wait_group 1;\n" ::: "memory");
        } else {
            asm volatile("cp.async.wait_group 0;\n" ::: "memory");
        }
        __syncthreads();

#pragma unroll
        for (int ks = 0; ks < 32; ks += 16) {
            uint32_t afr[2][4], bfr[4][2];
#pragma unroll
            for (int mt = 0; mt < 2; mt++) {
                ldsm_x4(afr[mt][0], afr[mt][1], afr[mt][2], afr[mt][3],
                        smem_u32(&As[buf][warpM * 32 + mt * 16 + lr16][ks + lk8]));
            }
#pragma unroll
            for (int ntp = 0; ntp < 2; ntp++) {
                uint32_t q0, q1, q2, q3;
                ldsm_x4(q0, q1, q2, q3,
                        smem_u32(&Bs[buf][warpN * 32 + ntp * 16 + lr16][ks + lk8]));
                bfr[2 * ntp][0]     = q0;
                bfr[2 * ntp + 1][0] = q1;
                bfr[2 * ntp][1]     = q2;
                bfr[2 * ntp + 1][1] = q3;
            }
#pragma unroll
            for (int mt = 0; mt < 2; mt++)
#pragma unroll
                for (int nt = 0; nt < 4; nt++)
                    mma_f16(acc[mt][nt], afr[mt], bfr[nt]);
        }
        __syncthreads();
    }

#pragma unroll
    for (int mt = 0; mt < 2; mt++) {
#pragma unroll
        for (int nt = 0; nt < 4; nt++) {
            int m0 = mrow + warpM * 32 + mt * 16 + g;
            int n0 = ncol + warpN * 32 + nt * 8 + 2 * t;
            if (n0 < N) {
                float b0 = bias[n0], b1 = bias[n0 + 1];
                if (m0 < M) {
                    C[(size_t)m0 * ldc + n0]     = acc[mt][nt][0] + b0;
                    C[(size_t)m0 * ldc + n0 + 1] = acc[mt][nt][1] + b1;
                }
                if (m0 + 8 < M) {
                    C[(size_t)(m0 + 8) * ldc + n0]     = acc[mt][nt][2] + b0;
                    C[(size_t)(m0 + 8) * ldc + n0 + 1] = acc[mt][nt][3] + b1;
                }
            }
        }
    }
}

// -------------------- recurrence: 4 clusters x 8 CTAs ------------------------
__global__ void __launch_bounds__(256, 1) __cluster_dims__(8, 1, 1)
k_rec(const float* __restrict__ w_hh) {
    __shared__ __align__(16) __half hs[16][264];   // h_prev (16 rows x 256)
    __shared__ float gbuf[16][132];                // gate exchange (128 cols)

    const int tid = threadIdx.x;
    const int lane = tid & 31;
    const int wid = tid >> 5;
    const int g = lane >> 2;
    const int t = lane & 3;
    const int lr16 = lane & 15;
    const int lk8 = (lane >> 4) * 8;
    const int rank = blockIdx.x & 7;
    const int grp = blockIdx.x >> 3;
    const int j0 = rank * 32;
    const int brow0 = grp * 16;

    uint32_t wb[2][16][2];
#pragma unroll
    for (int nt = 0; nt < 2; nt++) {
        int lc = wid * 16 + nt * 8 + g;
        int wrow = (lc >> 5) * 256 + j0 + (lc & 31);
        const float* wr = w_hh + (size_t)wrow * HH;
#pragma unroll
        for (int kt = 0; kt < 16; kt++) {
            __half2 h0 = __floats2half2_rn(wr[kt * 16 + 2 * t], wr[kt * 16 + 2 * t + 1]);
            __half2 h1 = __floats2half2_rn(wr[kt * 16 + 2 * t + 8], wr[kt * 16 + 2 * t + 9]);
            wb[nt][kt][0] = *(uint32_t*)&h0;
            wb[nt][kt][1] = *(uint32_t*)&h1;
        }
    }

    float creg[2] = {0.f, 0.f};
    const int crow = tid >> 4;
    const int cj2 = (tid & 15) * 2;
    int lc0[2], r0[2];
#pragma unroll
    for (int nt = 0; nt < 2; nt++) {
        lc0[nt] = wid * 16 + nt * 8 + 2 * t;
        r0[nt] = (lc0[nt] >> 5) * 256 + j0 + (lc0[nt] & 31);
    }

    for (int s = 0; s < SS; s++) {
        const float* gp = d_gpre + ((size_t)s * BB + brow0) * GG;
        float2 q0[2], q1[2];
#pragma unroll
        for (int nt = 0; nt < 2; nt++) {
            q0[nt] = *(const float2*)&gp[(size_t)g * GG + r0[nt]];
            q1[nt] = *(const float2*)&gp[(size_t)(g + 8) * GG + r0[nt]];
        }

        float accA[2][4] = {{0.f, 0.f, 0.f, 0.f}, {0.f, 0.f, 0.f, 0.f}};
        float accB[2][4] = {{0.f, 0.f, 0.f, 0.f}, {0.f, 0.f, 0.f, 0.f}};

        if (s > 0) {
            const uint4* src = (const uint4*)(d_Hall + ((size_t)(s - 1) * BB + brow0) * HH);
#pragma unroll
            for (int i = 0; i < 2; i++) {
                int c = tid + i * 256;
                int m = c >> 5, kc = c & 31;
                *(uint4*)&hs[m][kc * 8] = src[m * 32 + kc];
            }
            __syncthreads();
#pragma unroll
            for (int kt = 0; kt < 16; kt++) {
                uint32_t af[4];
                ldsm_x4(af[0], af[1], af[2], af[3],
                        smem_u32(&hs[lr16][kt * 16 + lk8]));
                float* d0 = (kt < 8) ? accA[0] : accB[0];
                float* d1 = (kt < 8) ? accA[1] : accB[1];
                mma_f16(d0, af, wb[0][kt]);
                mma_f16(d1, af, wb[1][kt]);
            }
        }

#pragma unroll
        for (int nt = 0; nt < 2; nt++) {
            gbuf[g][lc0[nt]]         = accA[nt][0] + accB[nt][0] + q0[nt].x;
            gbuf[g][lc0[nt] + 1]     = accA[nt][1] + accB[nt][1] + q0[nt].y;
            gbuf[g + 8][lc0[nt]]     = accA[nt][2] + accB[nt][2] + q1[nt].x;
            gbuf[g + 8][lc0[nt] + 1] = accA[nt][3] + accB[nt][3] + q1[nt].y;
        }
        __syncthreads();

        {
            float hv[2];
#pragma unroll
            for (int e = 0; e < 2; e++) {
                int jj = cj2 + e;
                float gi = gbuf[crow][jj],      gf = gbuf[crow][32 + jj];
                float gc = gbuf[crow][64 + jj], go = gbuf[crow][96 + jj];
                float ii = fast_sigmoid(gi);
                float ff = fast_sigmoid(gf);
                float gv = fast_tanh(gc);
                float oo = fast_sigmoid(go);
                float cn = ff * creg[e] + ii * gv;
                creg[e] = cn;
                hv[e] = oo * fast_tanh(cn);
            }
            __half2 hp = __floats2half2_rn(hv[0], hv[1]);
            *(uint32_t*)&d_Hall[((size_t)s * BB + brow0 + crow) * HH + j0 + cj2] =
                *(uint32_t*)&hp;
        }

        if (s + 1 < SS) {
            asm volatile("barrier.cluster.arrive.aligned;" ::: "memory");
            asm volatile("barrier.cluster.wait.aligned;" ::: "memory");
        }
    }
}

// -------------------- fused one-hot + log-softmax (register-cached row) ------
constexpr int V8 = VV / 8;   // 1250 uint4 groups
__global__ void __launch_bounds__(256) k_softmax(float* __restrict__ out) {
    const int r = blockIdx.x;
    const int tid = threadIdx.x;
    if (r >= MROWS) {                      // one-hot t=0 plane
        int b = r - MROWS;
        float* dst = out + (size_t)b * TT * VV;
        for (int v = tid * 4; v < VV; v += 1024) {
            float4 z = make_float4(0.f, 0.f, 0.f, 0.f);
            if (v == 0) z.y = 1.f;         // index 1 = START_ID
            __stcs((float4*)(dst + v), z);
        }
        return;
    }
    const int s = r >> 6, b = r & 63;
    const uint4* src = (const uint4*)(d_logits + (size_t)r * VV);

    uint4 vals[5];
    float m = -1e30f, sum = 0.f;
#pragma unroll
    for (int i = 0; i < 5; i++) {
        int c = tid + i * 256;
        if (c < V8) {
            uint4 u = src[c];
            vals[i] = u;
            float2 f0 = __half22float2(*(__half2*)&u.x);
            float2 f1 = __half22float2(*(__half2*)&u.y);
            float2 f2 = __half22float2(*(__half2*)&u.z);
            float2 f3 = __half22float2(*(__half2*)&u.w);
            float m8 = fmaxf(fmaxf(fmaxf(f0.x, f0.y), fmaxf(f1.x, f1.y)),
                             fmaxf(fmaxf(f2.x, f2.y), fmaxf(f3.x, f3.y)));
            if (m8 > m) { sum *= __expf(m - m8); m = m8; }
            sum += __expf(f0.x - m) + __expf(f0.y - m)
                 + __expf(f1.x - m) + __expf(f1.y - m)
                 + __expf(f2.x - m) + __expf(f2.y - m)
                 + __expf(f3.x - m) + __expf(f3.y - m);
        }
    }
#pragma unroll
    for (int o = 16; o; o >>= 1) {
        float mo = __shfl_xor_sync(0xffffffffu, m, o);
        float so = __shfl_xor_sync(0xffffffffu, sum, o);
        float M = fmaxf(m, mo);
        sum = sum * __expf(m - M) + so * __expf(mo - M);
        m = M;
    }
    __shared__ float sm_m[8], sm_s[8], s_lz;
    if ((tid & 31) == 0) { sm_m[tid >> 5] = m; sm_s[tid >> 5] = sum; }
    __syncthreads();
    if (tid == 0) {
        float M = sm_m[0], S = sm_s[0];
#pragma unroll
        for (int w = 1; w < 8; w++) {
            float mo = sm_m[w], so = sm_s[w];
            float MM = fmaxf(M, mo);
            S = S * __expf(M - MM) + so * __expf(mo - MM);
            M = MM;
        }
        s_lz = M + logf(S);
    }
    __syncthreads();
    const float lz = s_lz;
    float4* dst = (float4*)(out + ((size_t)b * TT + s + 1) * VV);
#pragma unroll
    for (int i = 0; i < 5; i++) {
        int c = tid + i * 256;
        if (c < V8) {
            uint4 u = vals[i];
            float2 f0 = __half22float2(*(__half2*)&u.x);
            float2 f1 = __half22float2(*(__half2*)&u.y);
            float2 f2 = __half22float2(*(__half2*)&u.z);
            float2 f3 = __half22float2(*(__half2*)&u.w);
            __stcs(&dst[2 * c],
                   make_float4(f0.x - lz, f0.y - lz, f1.x - lz, f1.y - lz));
            __stcs(&dst[2 * c + 1],
                   make_float4(f2.x - lz, f2.y - lz, f3.x - lz, f3.y - lz));
        }
    }
}

// -------------------- launch ------------------------------------------------
extern "C" void kernel_launch(void* const* d_in, const int* in_sizes, int n_in,
                              void* d_out, int out_size) {
    const float* X    = (const float*)d_in[0];
    const float* emb  = (const float*)d_in[1];
    const float* fc1w = (const float*)d_in[2];
    const float* fc1b = (const float*)d_in[3];
    const float* wih  = (const float*)d_in[4];
    const float* whh  = (const float*)d_in[5];
    const float* bih  = (const float*)d_in[6];
    const float* bhh  = (const float*)d_in[7];
    const float* fc2w = (const float*)d_in[8];
    const float* fc2b = (const float*)d_in[9];
    const int*   lab  = (const int*)d_in[10];
    float* out = (float*)d_out;

    __half *pAcat, *pHall, *pW2h, *pWihh, *pLogits;
    float *pBias2, *pGpre;
    cudaGetSymbolAddress((void**)&pAcat,   d_Acat);
    cudaGetSymbolAddress((void**)&pBias2,  d_bias2);
    cudaGetSymbolAddress((void**)&pGpre,   d_gpre);
    cudaGetSymbolAddress((void**)&pHall,   d_Hall);
    cudaGetSymbolAddress((void**)&pLogits, d_logits);
    cudaGetSymbolAddress((void**)&pW2h,    d_w2h);
    cudaGetSymbolAddress((void**)&pWihh,   d_wihh);

    k_fc1<<<dim3(8, 16), 256>>>(X, fc1w);
    k_fc1red<<<18, 256>>>(fc1b, lab, bih, bhh);
    k_cvtall<<<RALL / 256, 256>>>(emb, wih, fc2w);

    // gpre: [1984,1024] = Acat[1984,576] @ wihh[1024,576]^T + (bih+bhh)
    // 64x128 tiles -> grid (8,31) = 248 CTAs (vs 128): hides k-loop latency
    k_hgemm64<<<dim3(8, 31), 256>>>(pAcat, KAP, pWihh, KAP, pBias2,
                                    pGpre, GG, MROWS, GG, KAP);

    // recurrence: 32 CTAs = 4 clusters x 8 (cluster barrier between steps)
    k_rec<<<32, 256>>>(whh);

    // fc2: logits[1984,10000] (fp16) = Hall @ w2h^T + fc2b
    k_hgemm<__half><<<dim3(79, 16), 256>>>(pHall, HH, pW2h, HH, fc2b,
                                           pLogits, VV, MROWS, VV, HH);

    k_softmax<<<MROWS + BB, 256>>>(out);
}

// round 13
// speedup vs baseline: 1.5821x; 1.0041x over previous
#include <cuda_runtime.h>
#include <cuda_fp16.h>
#include <math.h>
#include <stdint.h>

// Problem dims
constexpr int BB = 64;
constexpr int TT = 32;
constexpr int SS = 31;     // scan steps (T-1)
constexpr int VV = 10000;
constexpr int EE = 300;
constexpr int HH = 256;
constexpr int FF = 4096;
constexpr int GG = 1024;   // 4*H
constexpr int KIN = HH + EE;   // 556
constexpr int KAP = 576;       // KIN padded to 32-multiple
constexpr int MROWS = SS * BB; // 1984

// -------------------- device scratch (static, no allocs) --------------------
__device__ float  d_Xp[BB * HH];
__device__ float  d_xpart[16 * BB * HH];
__device__ __half d_Acat[MROWS * KAP];     // [Xp | emb | 0] fp16
__device__ float  d_bias2[GG];             // b_ih + b_hh
__device__ float  d_gpre[MROWS * GG];      // precomputed gate inputs (fp32)
__device__ __half d_Hall[MROWS * HH];      // h history fp16 (fc2 A matrix)
__device__ __half d_logits[MROWS * VV];    // fc2 output, fp16 (40 MB)
__device__ int    d_labels[TT * BB];
__device__ __half d_w2h[VV * HH];          // fc2_w fp16
__device__ __half d_wihh[GG * KAP];        // w_ih fp16, K-padded

// -------------------- helpers ------------------------------------------------
__device__ __forceinline__ uint32_t smem_u32(const void* p) {
    return (uint32_t)__cvta_generic_to_shared(p);
}
__device__ __forceinline__ void cp16(void* smem_dst, const void* gsrc, bool pred) {
    uint32_t saddr = smem_u32(smem_dst);
    int sz = pred ? 16 : 0;
    asm volatile("cp.async.cg.shared.global [%0], [%1], 16, %2;\n"
                 :: "r"(saddr), "l"(gsrc), "r"(sz) : "memory");
}
__device__ __forceinline__ void mma_f16(float* d, const uint32_t* a, const uint32_t* b) {
    asm volatile(
        "mma.sync.aligned.m16n8k16.row.col.f32.f16.f16.f32 "
        "{%0,%1,%2,%3}, {%4,%5,%6,%7}, {%8,%9}, {%0,%1,%2,%3};"
        : "+f"(d[0]), "+f"(d[1]), "+f"(d[2]), "+f"(d[3])
        : "r"(a[0]), "r"(a[1]), "r"(a[2]), "r"(a[3]), "r"(b[0]), "r"(b[1]));
}
__device__ __forceinline__ void ldsm_x4(uint32_t& r0, uint32_t& r1,
                                        uint32_t& r2, uint32_t& r3, uint32_t addr) {
    asm volatile("ldmatrix.sync.aligned.m8n8.x4.shared.b16 {%0,%1,%2,%3}, [%4];"
                 : "=r"(r0), "=r"(r1), "=r"(r2), "=r"(r3) : "r"(addr));
}
__device__ __forceinline__ uint2 pack_h4(float4 v) {
    __half2 p0 = __floats2half2_rn(v.x, v.y);
    __half2 p1 = __floats2half2_rn(v.z, v.w);
    uint2 u;
    u.x = *(uint32_t*)&p0;
    u.y = *(uint32_t*)&p1;
    return u;
}
__device__ __forceinline__ float fast_tanh(float x) {
    float r;
    asm("tanh.approx.f32 %0, %1;" : "=f"(r) : "f"(x));
    return r;
}
__device__ __forceinline__ float fast_sigmoid(float x) {
    return 1.f / (1.f + __expf(-x));
}
#define CP_COMMIT() asm volatile("cp.async.commit_group;\n" ::: "memory")

// -------------------- fc1: Xp = X @ fc1_w.T + b (split-K SIMT) ---------------
__global__ void __launch_bounds__(256) k_fc1(const float* __restrict__ X,
                                             const float* __restrict__ W) {
    const int h0 = blockIdx.x * 32;
    const int kb = blockIdx.y;
    const int kbase = kb * 256;
    const int tid = threadIdx.x;
    __shared__ __align__(16) float Xs[32][68];
    __shared__ float Wsh[32][33];
    float acc[4][2];
#pragma unroll
    for (int q = 0; q < 4; q++) { acc[q][0] = 0.f; acc[q][1] = 0.f; }
    const int tb = (tid & 15) * 4;
    const int th = (tid >> 4) * 2;

    for (int t = 0; t < 8; t++) {
        int k0 = kbase + t * 32;
#pragma unroll
        for (int i = 0; i < 8; i++) {
            int idx = tid + i * 256;
            int b = idx >> 5, kk = idx & 31;
            Xs[kk][b] = X[(size_t)b * FF + k0 + kk];
        }
#pragma unroll
        for (int i = 0; i < 4; i++) {
            int idx = tid + i * 256;
            int hh = idx >> 5, kk = idx & 31;
            Wsh[kk][hh] = W[(size_t)(h0 + hh) * FF + k0 + kk];
        }
        __syncthreads();
#pragma unroll
        for (int kk = 0; kk < 32; kk++) {
            float4 x4 = *(const float4*)&Xs[kk][tb];
            float w0 = Wsh[kk][th], w1 = Wsh[kk][th + 1];
            acc[0][0] += x4.x * w0; acc[0][1] += x4.x * w1;
            acc[1][0] += x4.y * w0; acc[1][1] += x4.y * w1;
            acc[2][0] += x4.z * w0; acc[2][1] += x4.z * w1;
            acc[3][0] += x4.w * w0; acc[3][1] += x4.w * w1;
        }
        __syncthreads();
    }
#pragma unroll
    for (int q = 0; q < 4; q++)
#pragma unroll
        for (int j = 0; j < 2; j++)
            d_xpart[kb * (BB * HH) + (tb + q) * HH + h0 + th + j] = acc[q][j];
}

// -------------------- fc1 reduce + fused prep (blocks 16/17) -----------------
__global__ void k_fc1red(const float* __restrict__ fc1_b,
                         const int* __restrict__ lab,
                         const float* __restrict__ bih,
                         const float* __restrict__ bhh) {
    const int blk = blockIdx.x;
    const int tid = threadIdx.x;
    if (blk < 16) {
        int i4 = blk * 256 + tid;
        const float4* bp = (const float4*)fc1_b;
        float4 s = bp[i4 & 63];
#pragma unroll
        for (int kb = 0; kb < 16; kb++) {
            float4 p = ((const float4*)(d_xpart + kb * BB * HH))[i4];
            s.x += p.x; s.y += p.y; s.z += p.z; s.w += p.w;
        }
        ((float4*)d_Xp)[i4] = s;
    } else if (blk == 16) {
        __shared__ int is64;
        if (tid == 0) {
            int f = 1;
            for (int i = 1; i < 64 && f; i += 2)
                if (lab[i] != 0) f = 0;
            is64 = f;
        }
        __syncthreads();
        for (int i = tid; i < TT * BB; i += 256)
            d_labels[i] = is64 ? (int)(((const long long*)lab)[i]) : lab[i];
    } else {
        for (int i = tid; i < GG; i += 256)
            d_bias2[i] = bih[i] + bhh[i];
    }
}

// -------------------- merged elementwise: buildA + wih cvt + fc2w cvt --------
constexpr int AC4 = KAP / 4;               // 144 groups per row
constexpr int R1 = MROWS * AC4;            // 285696
constexpr int R2 = GG * AC4;               // 147456
constexpr int R3 = VV * HH / 4;            // 640000
constexpr int RALL = R1 + R2 + R3;         // 1073152
__global__ void __launch_bounds__(256) k_cvtall(const float* __restrict__ emb_table,
                                                const float* __restrict__ wih,
                                                const float* __restrict__ fc2w) {
    int idx = blockIdx.x * 256 + threadIdx.x;
    if (idx < R1) {                        // Acat = [Xp | emb | 0]
        int r = idx / AC4, c = idx - r * AC4;
        int s = r >> 6, b = r & 63;
        float4 v;
        if (c < 64) {
            v = ((const float4*)d_Xp)[b * 64 + c];
        } else if (c < 139) {
            int tok = (s == 0) ? 1 : d_labels[s * BB + b];   // START_ID = 1
            v = *(const float4*)(emb_table + (size_t)tok * EE + (c - 64) * 4);
        } else {
            v = make_float4(0.f, 0.f, 0.f, 0.f);
        }
        ((uint2*)d_Acat)[idx] = pack_h4(v);
    } else if (idx < R1 + R2) {            // w_ih -> fp16, K-padded
        int i = idx - R1;
        int r = i / AC4, c = i - r * AC4;
        float4 v = (c < 139) ? *(const float4*)(wih + (size_t)r * KIN + c * 4)
                             : make_float4(0.f, 0.f, 0.f, 0.f);
        ((uint2*)d_wihh)[i] = pack_h4(v);
    } else if (idx < RALL) {               // fc2_w -> fp16
        int i = idx - (R1 + R2);
        ((uint2*)d_w2h)[i] = pack_h4(((const float4*)fc2w)[i]);
    }
}

// -------------------- fp16 TC GEMM, 128x128 tile, 3-stage pipeline (fc2) -----
constexpr int ST2 = 3;
constexpr int H_ASTG = 128 * 40;                 // halves per A stage
constexpr int H_BSTG = 128 * 40;
constexpr int SMEM_HG = ST2 * (H_ASTG + H_BSTG) * 2;   // 61440 B
template <typename OT>
__global__ void __launch_bounds__(256) k_hgemm(
    const __half* __restrict__ A, int lda,
    const __half* __restrict__ B, int ldb,
    const float* __restrict__ bias,
    OT* __restrict__ C, int ldc,
    int M, int N, int K)
{
    extern __shared__ __half sm[];
    __half* AsB = sm;                      // [ST2][128][40]
    __half* BsB = sm + ST2 * H_ASTG;       // [ST2][128][40]

    const int tid = threadIdx.x;
    const int lane = tid & 31;
    const int warpId = tid >> 5;
    const int warpM = warpId & 3;
    const int warpN = warpId >> 2;
    const int g = lane >> 2;
    const int t = lane & 3;
    const int lr16 = lane & 15;
    const int lk8 = (lane >> 4) * 8;

    const int ncol = blockIdx.x * 128;
    const int mrow = blockIdx.y * 128;

    float acc[2][8][4];
#pragma unroll
    for (int mt = 0; mt < 2; mt++)
#pragma unroll
        for (int nt = 0; nt < 8; nt++)
#pragma unroll
            for (int q = 0; q < 4; q++) acc[mt][nt][q] = 0.f;

    const int NT = K >> 5;

    auto load_tile = [&](int st, int kt) {
        int k0 = kt << 5;
        __half* As = AsB + st * H_ASTG;
        __half* Bs = BsB + st * H_BSTG;
#pragma unroll
        for (int i = 0; i < 2; i++) {
            int c = tid + i * 256;
            int m = c >> 2, kc = (c & 3) * 8;
            cp16(As + m * 40 + kc, A + (size_t)(mrow + m) * lda + k0 + kc,
                 (mrow + m) < M);
        }
#pragma unroll
        for (int i = 0; i < 2; i++) {
            int c = tid + i * 256;
            int n = c >> 2, kc = (c & 3) * 8;
            cp16(Bs + n * 40 + kc, B + (size_t)(ncol + n) * ldb + k0 + kc,
                 (ncol + n) < N);
        }
    };

    // prefetch ST2-1 tiles (one commit each)
#pragma unroll
    for (int p = 0; p < ST2 - 1; p++) {
        if (p < NT) load_tile(p, p);
        CP_COMMIT();
    }

    for (int kt = 0; kt < NT; kt++) {
        int st = kt % ST2;
        if (kt + ST2 - 1 < NT) load_tile((kt + ST2 - 1) % ST2, kt + ST2 - 1);
        CP_COMMIT();                        // one group per iteration (maybe empty)
        asm volatile("cp.async.wait_group %0;\n" :: "n"(ST2 - 1) : "memory");
        __syncthreads();

        const __half* As = AsB + st * H_ASTG;
        const __half* Bs = BsB + st * H_BSTG;
#pragma unroll
        for (int ks = 0; ks < 32; ks += 16) {
            uint32_t afr[2][4], bfr[8][2];
#pragma unroll
            for (int mt = 0; mt < 2; mt++) {
                ldsm_x4(afr[mt][0], afr[mt][1], afr[mt][2], afr[mt][3],
                        smem_u32(As + (warpM * 32 + mt * 16 + lr16) * 40 + ks + lk8));
            }
#pragma unroll
            for (int ntp = 0; ntp < 4; ntp++) {
                uint32_t q0, q1, q2, q3;
                ldsm_x4(q0, q1, q2, q3,
                        smem_u32(Bs + (warpN * 64 + ntp * 16 + lr16) * 40 + ks + lk8));
                bfr[2 * ntp][0]     = q0;
                bfr[2 * ntp + 1][0] = q1;
                bfr[2 * ntp][1]     = q2;
                bfr[2 * ntp + 1][1] = q3;
            }
#pragma unroll
            for (int mt = 0; mt < 2; mt++)
#pragma unroll
                for (int nt = 0; nt < 8; nt++)
                    mma_f16(acc[mt][nt], afr[mt], bfr[nt]);
        }
        __syncthreads();
    }

#pragma unroll
    for (int mt = 0; mt < 2; mt++) {
#pragma unroll
        for (int nt = 0; nt < 8; nt++) {
            int m0 = mrow + warpM * 32 + mt * 16 + g;
            int n0 = ncol + warpN * 64 + nt * 8 + 2 * t;
            if (n0 < N) {
                float b0 = bias[n0], b1 = bias[n0 + 1];
                float v0 = acc[mt][nt][0] + b0, v1 = acc[mt][nt][1] + b1;
                float v2 = acc[mt][nt][2] + b0, v3 = acc[mt][nt][3] + b1;
                if (sizeof(OT) == 4) {
                    float* Cp = (float*)C;
                    if (m0 < M) {
                        Cp[(size_t)m0 * ldc + n0]     = v0;
                        Cp[(size_t)m0 * ldc + n0 + 1] = v1;
                    }
                    if (m0 + 8 < M) {
                        Cp[(size_t)(m0 + 8) * ldc + n0]     = v2;
                        Cp[(size_t)(m0 + 8) * ldc + n0 + 1] = v3;
                    }
                } else {
                    __half* Cp = (__half*)C;
                    if (m0 < M) {
                        __half2 h01 = __floats2half2_rn(v0, v1);
                        *(uint32_t*)&Cp[(size_t)m0 * ldc + n0] = *(uint32_t*)&h01;
                    }
                    if (m0 + 8 < M) {
                        __half2 h23 = __floats2half2_rn(v2, v3);
                        *(uint32_t*)&Cp[(size_t)(m0 + 8) * ldc + n0] = *(uint32_t*)&h23;
                    }
                }
            }
        }
    }
}

// -------------------- fp16 TC GEMM, 64x128 tile, 4-stage pipeline (gpre) -----
constexpr int ST4 = 4;
constexpr int H64_ASTG = 64 * 40;
constexpr int H64_BSTG = 128 * 40;
constexpr int SMEM_HG64 = ST4 * (H64_ASTG + H64_BSTG) * 2;   // 61440 B
__global__ void __launch_bounds__(256) k_hgemm64(
    const __half* __restrict__ A, int lda,
    const __half* __restrict__ B, int ldb,
    const float* __restrict__ bias,
    float* __restrict__ C, int ldc,
    int M, int N, int K)
{
    extern __shared__ __half sm[];
    __half* AsB = sm;                      // [ST4][64][40]
    __half* BsB = sm + ST4 * H64_ASTG;     // [ST4][128][40]

    const int tid = threadIdx.x;
    const int lane = tid & 31;
    const int warpId = tid >> 5;
    const int warpM = warpId & 1;    // 2 M-warps x 32 rows
    const int warpN = warpId >> 1;   // 4 N-warps x 32 cols
    const int g = lane >> 2;
    const int t = lane & 3;
    const int lr16 = lane & 15;
    const int lk8 = (lane >> 4) * 8;

    const int ncol = blockIdx.x * 128;
    const int mrow = blockIdx.y * 64;

    float acc[2][4][4];
#pragma unroll
    for (int mt = 0; mt < 2; mt++)
#pragma unroll
        for (int nt = 0; nt < 4; nt++)
#pragma unroll
            for (int q = 0; q < 4; q++) acc[mt][nt][q] = 0.f;

    const int NT = K >> 5;

    auto load_tile = [&](int st, int kt) {
        int k0 = kt << 5;
        __half* As = AsB + st * H64_ASTG;
        __half* Bs = BsB + st * H64_BSTG;
        {
            int c = tid;
            int m = c >> 2, kc = (c & 3) * 8;
            cp16(As + m * 40 + kc, A + (size_t)(mrow + m) * lda + k0 + kc,
                 (mrow + m) < M);
        }
#pragma unroll
        for (int i = 0; i < 2; i++) {
            int c = tid + i * 256;
            int n = c >> 2, kc = (c & 3) * 8;
            cp16(Bs + n * 40 + kc, B + (size_t)(ncol + n) * ldb + k0 + kc,
                 (ncol + n) < N);
        }
    };

#pragma unroll
    for (int p = 0; p < ST4 - 1; p++) {
        if (p < NT) load_tile(p, p);
        CP_COMMIT();
    }

    for (int kt = 0; kt < NT; kt++) {
        int st = kt % ST4;
        if (kt + ST4 - 1 < NT) load_tile((kt + ST4 - 1) % ST4, kt + ST4 - 1);
        CP_COMMIT();
        asm volatile("cp.async.wait_group %0;\n" :: "n"(ST4 - 1) : "memory");
        __syncthreads();

        const __half* As = AsB + st * H64_ASTG;
        const __half* Bs = BsB + st * H64_BSTG;
#pragma unroll
        for (int ks = 0; ks < 32; ks += 16) {
            uint32_t afr[2][4], bfr[4][2];
#pragma unroll
            for (int mt = 0; mt < 2; mt++) {
                ldsm_x4(afr[mt][0], afr[mt][1], afr[mt][2], afr[mt][3],
                        smem_u32(As + (warpM * 32 + mt * 16 + lr16) * 40 + ks + lk8));
            }
#pragma unroll
            for (int ntp = 0; ntp < 2; ntp++) {
                uint32_t q0, q1, q2, q3;
                ldsm_x4(q0, q1, q2, q3,
                        smem_u32(Bs + (warpN * 32 + ntp * 16 + lr16) * 40 + ks + lk8));
                bfr[2 * ntp][0]     = q0;
                bfr[2 * ntp + 1][0] = q1;
                bfr[2 * ntp][1]     = q2;
                bfr[2 * ntp + 1][1] = q3;
            }
#pragma unroll
            for (int mt = 0; mt < 2; mt++)
#pragma unroll
                for (int nt = 0; nt < 4; nt++)
                    mma_f16(acc[mt][nt], afr[mt], bfr[nt]);
        }
        __syncthreads();
    }

#pragma unroll
    for (int mt = 0; mt < 2; mt++) {
#pragma unroll
        for (int nt = 0; nt < 4; nt++) {
            int m0 = mrow + warpM * 32 + mt * 16 + g;
            int n0 = ncol + warpN * 32 + nt * 8 + 2 * t;
            if (n0 < N) {
                float b0 = bias[n0], b1 = bias[n0 + 1];
                if (m0 < M) {
                    C[(size_t)m0 * ldc + n0]     = acc[mt][nt][0] + b0;
                    C[(size_t)m0 * ldc + n0 + 1] = acc[mt][nt][1] + b1;
                }
                if (m0 + 8 < M) {
                    C[(size_t)(m0 + 8) * ldc + n0]     = acc[mt][nt][2] + b0;
                    C[(size_t)(m0 + 8) * ldc + n0 + 1] = acc[mt][nt][3] + b1;
                }
            }
        }
    }
}

// -------------------- recurrence: 4 clusters x 8 CTAs ------------------------
__global__ void __launch_bounds__(256, 1) __cluster_dims__(8, 1, 1)
k_rec(const float* __restrict__ w_hh) {
    __shared__ __align__(16) __half hs[16][264];   // h_prev (16 rows x 256)
    __shared__ float gbuf[16][132];                // gate exchange (128 cols)

    const int tid = threadIdx.x;
    const int lane = tid & 31;
    const int wid = tid >> 5;
    const int g = lane >> 2;
    const int t = lane & 3;
    const int lr16 = lane & 15;
    const int lk8 = (lane >> 4) * 8;
    const int rank = blockIdx.x & 7;
    const int grp = blockIdx.x >> 3;
    const int j0 = rank * 32;
    const int brow0 = grp * 16;

    uint32_t wb[2][16][2];
#pragma unroll
    for (int nt = 0; nt < 2; nt++) {
        int lc = wid * 16 + nt * 8 + g;
        int wrow = (lc >> 5) * 256 + j0 + (lc & 31);
        const float* wr = w_hh + (size_t)wrow * HH;
#pragma unroll
        for (int kt = 0; kt < 16; kt++) {
            __half2 h0 = __floats2half2_rn(wr[kt * 16 + 2 * t], wr[kt * 16 + 2 * t + 1]);
            __half2 h1 = __floats2half2_rn(wr[kt * 16 + 2 * t + 8], wr[kt * 16 + 2 * t + 9]);
            wb[nt][kt][0] = *(uint32_t*)&h0;
            wb[nt][kt][1] = *(uint32_t*)&h1;
        }
    }

    float creg[2] = {0.f, 0.f};
    const int crow = tid >> 4;
    const int cj2 = (tid & 15) * 2;
    int lc0[2], r0[2];
#pragma unroll
    for (int nt = 0; nt < 2; nt++) {
        lc0[nt] = wid * 16 + nt * 8 + 2 * t;
        r0[nt] = (lc0[nt] >> 5) * 256 + j0 + (lc0[nt] & 31);
    }

    for (int s = 0; s < SS; s++) {
        const float* gp = d_gpre + ((size_t)s * BB + brow0) * GG;
        float2 q0[2], q1[2];
#pragma unroll
        for (int nt = 0; nt < 2; nt++) {
            q0[nt] = *(const float2*)&gp[(size_t)g * GG + r0[nt]];
            q1[nt] = *(const float2*)&gp[(size_t)(g + 8) * GG + r0[nt]];
        }

        float accA[2][4] = {{0.f, 0.f, 0.f, 0.f}, {0.f, 0.f, 0.f, 0.f}};
        float accB[2][4] = {{0.f, 0.f, 0.f, 0.f}, {0.f, 0.f, 0.f, 0.f}};

        if (s > 0) {
            const uint4* src = (const uint4*)(d_Hall + ((size_t)(s - 1) * BB + brow0) * HH);
#pragma unroll
            for (int i = 0; i < 2; i++) {
                int c = tid + i * 256;
                int m = c >> 5, kc = c & 31;
                *(uint4*)&hs[m][kc * 8] = src[m * 32 + kc];
            }
            __syncthreads();
#pragma unroll
            for (int kt = 0; kt < 16; kt++) {
                uint32_t af[4];
                ldsm_x4(af[0], af[1], af[2], af[3],
                        smem_u32(&hs[lr16][kt * 16 + lk8]));
                float* d0 = (kt < 8) ? accA[0] : accB[0];
                float* d1 = (kt < 8) ? accA[1] : accB[1];
                mma_f16(d0, af, wb[0][kt]);
                mma_f16(d1, af, wb[1][kt]);
            }
        }

#pragma unroll
        for (int nt = 0; nt < 2; nt++) {
            gbuf[g][lc0[nt]]         = accA[nt][0] + accB[nt][0] + q0[nt].x;
            gbuf[g][lc0[nt] + 1]     = accA[nt][1] + accB[nt][1] + q0[nt].y;
            gbuf[g + 8][lc0[nt]]     = accA[nt][2] + accB[nt][2] + q1[nt].x;
            gbuf[g + 8][lc0[nt] + 1] = accA[nt][3] + accB[nt][3] + q1[nt].y;
        }
        __syncthreads();

        {
            float hv[2];
#pragma unroll
            for (int e = 0; e < 2; e++) {
                int jj = cj2 + e;
                float gi = gbuf[crow][jj],      gf = gbuf[crow][32 + jj];
                float gc = gbuf[crow][64 + jj], go = gbuf[crow][96 + jj];
                float ii = fast_sigmoid(gi);
                float ff = fast_sigmoid(gf);
                float gv = fast_tanh(gc);
                float oo = fast_sigmoid(go);
                float cn = ff * creg[e] + ii * gv;
                creg[e] = cn;
                hv[e] = oo * fast_tanh(cn);
            }
            __half2 hp = __floats2half2_rn(hv[0], hv[1]);
            *(uint32_t*)&d_Hall[((size_t)s * BB + brow0 + crow) * HH + j0 + cj2] =
                *(uint32_t*)&hp;
        }

        if (s + 1 < SS) {
            asm volatile("barrier.cluster.arrive.aligned;" ::: "memory");
            asm volatile("barrier.cluster.wait.aligned;" ::: "memory");
        }
    }
}

// -------------------- fused one-hot + log-softmax (register-cached row) ------
constexpr int V8 = VV / 8;   // 1250 uint4 groups
__global__ void __launch_bounds__(256) k_softmax(float* __restrict__ out) {
    const int r = blockIdx.x;
    const int tid = threadIdx.x;
    if (r >= MROWS) {                      // one-hot t=0 plane
        int b = r - MROWS;
        float* dst = out + (size_t)b * TT * VV;
        for (int v = tid * 4; v < VV; v += 1024) {
            float4 z = make_float4(0.f, 0.f, 0.f, 0.f);
            if (v == 0) z.y = 1.f;         // index 1 = START_ID
            __stcs((float4*)(dst + v), z);
        }
        return;
    }
    const int s = r >> 6, b = r & 63;
    const uint4* src = (const uint4*)(d_logits + (size_t)r * VV);

    uint4 vals[5];
    float m = -1e30f, sum = 0.f;
#pragma unroll
    for (int i = 0; i < 5; i++) {
        int c = tid + i * 256;
        if (c < V8) {
            uint4 u = src[c];
            vals[i] = u;
            float2 f0 = __half22float2(*(__half2*)&u.x);
            float2 f1 = __half22float2(*(__half2*)&u.y);
            float2 f2 = __half22float2(*(__half2*)&u.z);
            float2 f3 = __half22float2(*(__half2*)&u.w);
            float m8 = fmaxf(fmaxf(fmaxf(f0.x, f0.y), fmaxf(f1.x, f1.y)),
                             fmaxf(fmaxf(f2.x, f2.y), fmaxf(f3.x, f3.y)));
            if (m8 > m) { sum *= __expf(m - m8); m = m8; }
            sum += __expf(f0.x - m) + __expf(f0.y - m)
                 + __expf(f1.x - m) + __expf(f1.y - m)
                 + __expf(f2.x - m) + __expf(f2.y - m)
                 + __expf(f3.x - m) + __expf(f3.y - m);
        }
    }
#pragma unroll
    for (int o = 16; o; o >>= 1) {
        float mo = __shfl_xor_sync(0xffffffffu, m, o);
        float so = __shfl_xor_sync(0xffffffffu, sum, o);
        float M = fmaxf(m, mo);
        sum = sum * __expf(m - M) + so * __expf(mo - M);
        m = M;
    }
    __shared__ float sm_m[8], sm_s[8], s_lz;
    if ((tid & 31) == 0) { sm_m[tid >> 5] = m; sm_s[tid >> 5] = sum; }
    __syncthreads();
    if (tid == 0) {
        float M = sm_m[0], S = sm_s[0];
#pragma unroll
        for (int w = 1; w < 8; w++) {
            float mo = sm_m[w], so = sm_s[w];
            float MM = fmaxf(M, mo);
            S = S * __expf(M - MM) + so * __expf(mo - MM);
            M = MM;
        }
        s_lz = M + logf(S);
    }
    __syncthreads();
    const float lz = s_lz;
    float4* dst = (float4*)(out + ((size_t)b * TT + s + 1) * VV);
#pragma unroll
    for (int i = 0; i < 5; i++) {
        int c = tid + i * 256;
        if (c < V8) {
            uint4 u = vals[i];
            float2 f0 = __half22float2(*(__half2*)&u.x);
            float2 f1 = __half22float2(*(__half2*)&u.y);
            float2 f2 = __half22float2(*(__half2*)&u.z);
            float2 f3 = __half22float2(*(__half2*)&u.w);
            __stcs(&dst[2 * c],
                   make_float4(f0.x - lz, f0.y - lz, f1.x - lz, f1.y - lz));
            __stcs(&dst[2 * c + 1],
                   make_float4(f2.x - lz, f2.y - lz, f3.x - lz, f3.y - lz));
        }
    }
}

// -------------------- launch ------------------------------------------------
extern "C" void kernel_launch(void* const* d_in, const int* in_sizes, int n_in,
                              void* d_out, int out_size) {
    const float* X    = (const float*)d_in[0];
    const float* emb  = (const float*)d_in[1];
    const float* fc1w = (const float*)d_in[2];
    const float* fc1b = (const float*)d_in[3];
    const float* wih  = (const float*)d_in[4];
    const float* whh  = (const float*)d_in[5];
    const float* bih  = (const float*)d_in[6];
    const float* bhh  = (const float*)d_in[7];
    const float* fc2w = (const float*)d_in[8];
    const float* fc2b = (const float*)d_in[9];
    const int*   lab  = (const int*)d_in[10];
    float* out = (float*)d_out;

    __half *pAcat, *pHall, *pW2h, *pWihh, *pLogits;
    float *pBias2, *pGpre;
    cudaGetSymbolAddress((void**)&pAcat,   d_Acat);
    cudaGetSymbolAddress((void**)&pBias2,  d_bias2);
    cudaGetSymbolAddress((void**)&pGpre,   d_gpre);
    cudaGetSymbolAddress((void**)&pHall,   d_Hall);
    cudaGetSymbolAddress((void**)&pLogits, d_logits);
    cudaGetSymbolAddress((void**)&pW2h,    d_w2h);
    cudaGetSymbolAddress((void**)&pWihh,   d_wihh);

    static int attr_set = 0;
    if (!attr_set) {
        cudaFuncSetAttribute(k_hgemm<__half>,
                             cudaFuncAttributeMaxDynamicSharedMemorySize, SMEM_HG);
        cudaFuncSetAttribute(k_hgemm<float>,
                             cudaFuncAttributeMaxDynamicSharedMemorySize, SMEM_HG);
        cudaFuncSetAttribute(k_hgemm64,
                             cudaFuncAttributeMaxDynamicSharedMemorySize, SMEM_HG64);
        attr_set = 1;
    }

    k_fc1<<<dim3(8, 16), 256>>>(X, fc1w);
    k_fc1red<<<18, 256>>>(fc1b, lab, bih, bhh);
    k_cvtall<<<RALL / 256, 256>>>(emb, wih, fc2w);

    // gpre: [1984,1024] = Acat[1984,576] @ wihh[1024,576]^T + (bih+bhh)
    // 64x128 tiles, 4-stage cp.async pipeline
    k_hgemm64<<<dim3(8, 31), 256, SMEM_HG64>>>(pAcat, KAP, pWihh, KAP, pBias2,
                                               pGpre, GG, MROWS, GG, KAP);

    // recurrence: 32 CTAs = 4 clusters x 8 (cluster barrier between steps)
    k_rec<<<32, 256>>>(whh);

    // fc2: logits[1984,10000] (fp16) = Hall @ w2h^T + fc2b, 3-stage pipeline
    k_hgemm<__half><<<dim3(79, 16), 256, SMEM_HG>>>(pHall, HH, pW2h, HH, fc2b,
                                                    pLogits, VV, MROWS, VV, HH);

    k_softmax<<<MROWS + BB, 256>>>(out);
}